// round 7
// baseline (speedup 1.0000x reference)
#include <cuda_runtime.h>
#include <cstdint>

// Problem constants
static constexpr int   B_   = 16;
static constexpr int   N_   = 1024;
static constexpr float TAU_ = 0.5f;
static constexpr float EPS_ = 1e-10f;
static constexpr int   NSQ  = N_ * N_;        // 1048576
static constexpr int   NB   = B_ * N_;        // 16384 nodes total

// ---------------------------------------------------------------------------
// Scratch (device globals; allocation is forbidden)
// xeff layout per node (384 floats):
//   [  0.. 63] xin
//   [ 64..127] h        (pass 1)  ->  r*h   (overwritten by k4b epilogue)
//   [128..191] P0x = ((adj @x)+x)_xin * invc
//   [192..255] P0h (pass 1)       ->  Q0 = ((adj @rh)+rh)*invc (k6 epilogue)
//   [256..319] P1x = ((adjT@x)+x)_xin * invr
//   [320..383] P1h (pass 1)       ->  Q1 = ((adjT@rh)+rh)*invr (k6 epilogue)
// ---------------------------------------------------------------------------
__device__ float g_adj  [B_ * NSQ];          // 64 MB  adj[b,i,j]
__device__ float g_rowsum[NB];               // sum_j adj[i,j]
__device__ float g_colsum[NB];               // sum_i adj[i,j]
__device__ float g_xeff [NB * 384];
__device__ float g_u    [NB * 64];           // update gate
__device__ float g_w1t  [384 * 128];         // gate weights, (k,o'), o' interleaved r/u
__device__ float g_w2t  [384 * 64];          // candidate weights, (k,o)
__device__ float g_b1   [128];               // interleaved r/u bias
__device__ float g_b2   [64];

// ---------------------------------------------------------------------------
// cp.async helpers
// ---------------------------------------------------------------------------
__device__ __forceinline__ void cp_async16(void* smem_dst, const void* gsrc)
{
    uint32_t s = (uint32_t)__cvta_generic_to_shared(smem_dst);
    asm volatile("cp.async.cg.shared.global [%0], [%1], 16;\n" :: "r"(s), "l"(gsrc));
}
__device__ __forceinline__ void cp_commit() { asm volatile("cp.async.commit_group;\n"); }
__device__ __forceinline__ void cp_wait1()  { asm volatile("cp.async.wait_group 1;\n"); }
__device__ __forceinline__ void cp_wait0()  { asm volatile("cp.async.wait_group 0;\n"); }

__device__ __forceinline__ void mma_m16n8k8(float c[4],
                                            uint32_t a0, uint32_t a1, uint32_t a2, uint32_t a3,
                                            uint32_t b0, uint32_t b1)
{
    asm volatile("mma.sync.aligned.m16n8k8.row.col.f32.tf32.tf32.f32 "
                 "{%0,%1,%2,%3}, {%4,%5,%6,%7}, {%8,%9}, {%0,%1,%2,%3};\n"
                 : "+f"(c[0]), "+f"(c[1]), "+f"(c[2]), "+f"(c[3])
                 : "r"(a0), "r"(a1), "r"(a2), "r"(a3), "r"(b0), "r"(b1));
}

// ---------------------------------------------------------------------------
// Pipelined TF32 MMA core (double-buffered cp.async, BK=16) with
// register-level fragment double-buffering (ks-step prefetch).
//   AKM=false: A row-major (element (m,k) at A[m*ldA+k]); smem A [BM][20]
//   AKM=true : A K-major   (element (m,k) at A[k*ldA+m]); smem A [16][BM+8]
// Raw fp32 bits feed the TF32 MMA (hardware truncates to 19 bits).
// Epi(rowGlobal, colLocal, v0, v1, v2, v3): values at (row,col),(row,col+1),
// (row+8,col),(row+8,col+1); col is always even.
// ---------------------------------------------------------------------------
template<int BM, int BN, int WARPS_M, int WARPS_N, bool AKM, class Epi>
__device__ __forceinline__ void mma_pipe(const float* __restrict__ A,
                                         const float* __restrict__ X,
                                         int Kd, int ldA, int ldX,
                                         int rowBase, char* sbuf, Epi epi)
{
    constexpr int BK      = 16;
    constexpr int KSTEPS  = BK / 8;            // 2
    constexpr int THREADS = WARPS_M * WARPS_N * 32;
    constexpr int WM = BM / WARPS_M;
    constexpr int WN = BN / WARPS_N;
    constexpr int MI = WM / 16;
    constexpr int NI = WN / 8;
    constexpr int A_ST_RM = BK + 4;            // 20 floats
    constexpr int A_ST_KM = BM + 8;
    constexpr int A_FLOATS = AKM ? BK * A_ST_KM : BM * A_ST_RM;
    constexpr int B_ST = BN + 8;
    constexpr int B_FLOATS = BK * B_ST;

    float* As0 = (float*)sbuf;
    float* As1 = As0 + A_FLOATS;
    float* Bs0 = As1 + A_FLOATS;
    float* Bs1 = Bs0 + B_FLOATS;

    const int tid  = threadIdx.x;
    const int lane = tid & 31;
    const int w    = tid >> 5;
    const int wm   = w / WARPS_N;
    const int wn   = w % WARPS_N;
    const int grp  = lane >> 2;     // 0..7
    const int qid  = lane & 3;      // 0..3

    float acc[MI][NI][4];
#pragma unroll
    for (int mi = 0; mi < MI; ++mi)
#pragma unroll
        for (int ni = 0; ni < NI; ++ni)
#pragma unroll
            for (int r = 0; r < 4; ++r) acc[mi][ni][r] = 0.f;

    auto load_stage = [&](int s, int k0) {
        float* As = s ? As1 : As0;
        float* Bs = s ? Bs1 : Bs0;
        if (AKM) {
#pragma unroll
            for (int i = tid; i < BK * (BM / 4); i += THREADS) {
                int kr = i / (BM / 4), mq = i % (BM / 4);
                cp_async16(As + kr * A_ST_KM + mq * 4,
                           A + (size_t)(k0 + kr) * ldA + rowBase + mq * 4);
            }
        } else {
#pragma unroll
            for (int i = tid; i < BM * (BK / 4); i += THREADS) {
                int m = i / (BK / 4), kq = i % (BK / 4);
                cp_async16(As + m * A_ST_RM + kq * 4,
                           A + (size_t)(rowBase + m) * ldA + k0 + kq * 4);
            }
        }
#pragma unroll
        for (int i = tid; i < BK * (BN / 4); i += THREADS) {
            int kr = i / (BN / 4), cq = i % (BN / 4);
            cp_async16(Bs + kr * B_ST + cq * 4,
                       X + (size_t)(k0 + kr) * ldX + cq * 4);
        }
    };

    // fragment loader for one ks step
    uint32_t afr[2][MI][4];
    uint32_t bfr[2][NI][2];
    auto ldfrag = [&](const float* As, const float* Bs, int ks, int buf) {
        const int kb = ks * 8 + qid;
#pragma unroll
        for (int mi = 0; mi < MI; ++mi) {
            int row = wm * WM + mi * 16 + grp;
            if (AKM) {
                afr[buf][mi][0] = __float_as_uint(As[(kb    ) * A_ST_KM + row    ]);
                afr[buf][mi][1] = __float_as_uint(As[(kb    ) * A_ST_KM + row + 8]);
                afr[buf][mi][2] = __float_as_uint(As[(kb + 4) * A_ST_KM + row    ]);
                afr[buf][mi][3] = __float_as_uint(As[(kb + 4) * A_ST_KM + row + 8]);
            } else {
                afr[buf][mi][0] = __float_as_uint(As[(row    ) * A_ST_RM + kb    ]);
                afr[buf][mi][1] = __float_as_uint(As[(row + 8) * A_ST_RM + kb    ]);
                afr[buf][mi][2] = __float_as_uint(As[(row    ) * A_ST_RM + kb + 4]);
                afr[buf][mi][3] = __float_as_uint(As[(row + 8) * A_ST_RM + kb + 4]);
            }
        }
#pragma unroll
        for (int ni = 0; ni < NI; ++ni) {
            int col = wn * WN + ni * 8 + grp;
            bfr[buf][ni][0] = __float_as_uint(Bs[(kb    ) * B_ST + col]);
            bfr[buf][ni][1] = __float_as_uint(Bs[(kb + 4) * B_ST + col]);
        }
    };

    load_stage(0, 0);
    cp_commit();

    const int nIter = Kd / BK;
    for (int it = 0; it < nIter; ++it) {
        const int cur = it & 1;
        if (it + 1 < nIter) {
            load_stage(cur ^ 1, (it + 1) * BK);
            cp_commit();
            cp_wait1();
        } else {
            cp_wait0();
        }
        __syncthreads();

        const float* As = cur ? As1 : As0;
        const float* Bs = cur ? Bs1 : Bs0;

        ldfrag(As, Bs, 0, 0);
#pragma unroll
        for (int ks = 0; ks < KSTEPS; ++ks) {
            if (ks + 1 < KSTEPS) ldfrag(As, Bs, ks + 1, (ks + 1) & 1);
            const int buf = ks & 1;
#pragma unroll
            for (int mi = 0; mi < MI; ++mi)
#pragma unroll
                for (int ni = 0; ni < NI; ++ni)
                    mma_m16n8k8(acc[mi][ni],
                                afr[buf][mi][0], afr[buf][mi][1],
                                afr[buf][mi][2], afr[buf][mi][3],
                                bfr[buf][ni][0], bfr[buf][ni][1]);
        }
        __syncthreads();
    }

#pragma unroll
    for (int mi = 0; mi < MI; ++mi)
#pragma unroll
        for (int ni = 0; ni < NI; ++ni) {
            int row = rowBase + wm * WM + mi * 16 + grp;
            int col = wn * WN + ni * 8 + 2 * qid;
            epi(row, col, acc[mi][ni][0], acc[mi][ni][1], acc[mi][ni][2], acc[mi][ni][3]);
        }
}

// ---------------------------------------------------------------------------
// K0: fold weights. Reference's diffusion appends `prev` twice (A^2 x unused)
// so steps 1+2 share Ax -> pre-sum those weight columns. w1t output columns
// interleaved: o'=2o -> r-channel o, o'=2o+1 -> u-channel o (orig row o+64).
// ---------------------------------------------------------------------------
__global__ void k0_prep(const float* __restrict__ W0, const float* __restrict__ b0,
                        const float* __restrict__ W1, const float* __restrict__ b1,
                        const float* __restrict__ Wc0, const float* __restrict__ bc0,
                        const float* __restrict__ Wc1, const float* __restrict__ bc1)
{
    int idx    = blockIdx.x * blockDim.x + threadIdx.x;
    int stride = gridDim.x * blockDim.x;

    for (int i = idx; i < 384 * 128; i += stride) {
        int k = i / 128, o = i % 128;
        int orig = (o & 1) ? (o >> 1) + 64 : (o >> 1);     // interleave r/u
        float v;
        if (k < 128)       { int c = k;        v = W0[orig*384 + 3*c]     + W1[orig*384 + 3*c];     }
        else if (k < 256)  { int c = k - 128;  v = W0[orig*384 + 3*c + 1] + W0[orig*384 + 3*c + 2]; }
        else               { int c = k - 256;  v = W1[orig*384 + 3*c + 1] + W1[orig*384 + 3*c + 2]; }
        g_w1t[i] = v;
    }
    for (int i = idx; i < 384 * 64; i += stride) {
        int k = i / 64, o = i % 64;
        float v;
        if (k < 128)       { int c = k;        v = Wc0[o*384 + 3*c]     + Wc1[o*384 + 3*c];     }
        else if (k < 256)  { int c = k - 128;  v = Wc0[o*384 + 3*c + 1] + Wc0[o*384 + 3*c + 2]; }
        else               { int c = k - 256;  v = Wc1[o*384 + 3*c + 1] + Wc1[o*384 + 3*c + 2]; }
        g_w2t[i] = v;
    }
    for (int i = idx; i < 128; i += stride) {
        int orig = (i & 1) ? (i >> 1) + 64 : (i >> 1);
        g_b1[i] = b0[orig] + b1[orig];
    }
    for (int i = idx; i < 64;  i += stride) g_b2[i] = bc0[i] + bc1[i];
    for (int i = idx; i < NB;  i += stride) { g_rowsum[i] = 0.f; g_colsum[i] = 0.f; }
}

// ---------------------------------------------------------------------------
// K1: Gumbel-softmax adjacency + row/col sums (fused).
// z_i = l_i - log(g_i), g_i = EPS - log(u_i + EPS)
// adj = softmax(z/tau)[0] = 1 / (1 + exp((z1 - z0)/tau))
// ---------------------------------------------------------------------------
__global__ void k1_gumbel(const float* __restrict__ logits,
                          const float* __restrict__ unoise)
{
    __shared__ float scol[8][32];

    const int b  = blockIdx.z;
    const int i0 = blockIdx.y * 32;
    const int j0 = blockIdx.x * 32;
    const int tx = threadIdx.x;
    const int ty = threadIdx.y;

    const float2* lg = reinterpret_cast<const float2*>(logits) + (size_t)b * NSQ;
    const float2* un = reinterpret_cast<const float2*>(unoise) + (size_t)b * NSQ;

    float vals[4];
#pragma unroll
    for (int sI = 0; sI < 4; ++sI) {
        int row  = ty + 8 * sI;
        size_t e = (size_t)(i0 + row) * N_ + (j0 + tx);
        float2 l = lg[e];
        float2 u = un[e];
        float g0 = EPS_ - __logf(u.x + EPS_);
        float g1 = EPS_ - __logf(u.y + EPS_);
        float t  = ((l.y - l.x) + (__logf(g0) - __logf(g1))) * (1.0f / TAU_);
        float a  = 1.0f / (1.0f + __expf(t));
        vals[sI] = a;
        g_adj[(size_t)b * NSQ + e] = a;
    }

#pragma unroll
    for (int sI = 0; sI < 4; ++sI) {
        float v = vals[sI];
#pragma unroll
        for (int o = 16; o > 0; o >>= 1) v += __shfl_down_sync(0xffffffffu, v, o);
        if (tx == 0) atomicAdd(&g_rowsum[b * N_ + i0 + ty + 8 * sI], v);
    }

    scol[ty][tx] = vals[0] + vals[1] + vals[2] + vals[3];
    __syncthreads();
    if (ty == 0) {
        float t2 = 0.f;
#pragma unroll
        for (int w = 0; w < 8; ++w) t2 += scol[w][tx];
        atomicAdd(&g_colsum[b * N_ + j0 + tx], t2);
    }
}

// ---------------------------------------------------------------------------
// K2: write xin -> xeff[0..63], h -> xeff[64..127]
// ---------------------------------------------------------------------------
__global__ void k2_xcat(const float* __restrict__ inp, const float* __restrict__ hx)
{
    size_t idx = (size_t)blockIdx.x * blockDim.x + threadIdx.x;
    if (idx >= (size_t)NB * 128) return;
    size_t node = idx >> 7;
    int c = (int)(idx & 127);
    float v = (c < 64) ? inp[node * 64 + c] : hx[node * 64 + (c - 64)];
    g_xeff[node * 384 + c] = v;
}

// ---------------------------------------------------------------------------
// Shared-buffer sizes (bytes). BM=64 everywhere.
//   BN=128: A max(64*20, 16*72)=1280 fl; B 16*136=2176 fl -> 2 stages 27648 B
//   BN=64 : A 1280 fl; B 16*72=1152 fl                   -> 2 stages 19456 B
// ---------------------------------------------------------------------------
static constexpr int SB_BN128 = (1280 + 2176) * 2 * 4;
static constexpr int SB_BN64  = (1280 + 1152) * 2 * 4;

// ---------------------------------------------------------------------------
// K3: pass-1 SpMM pair. sel0: p0 = adj@xcat, scaled by 1/(colsum+1), into
// xeff cols 128..255. sel1: p1 = adjT@xcat, 1/(rowsum+1), cols 256..383.
// Epilogue adds the identity term (x) before scaling.
// ---------------------------------------------------------------------------
__global__ __launch_bounds__(256, 2)
void k3_spmm()
{
    __shared__ __align__(16) char sbuf[SB_BN128];
    int z   = blockIdx.z;
    int b   = z & 15;
    int sel = z >> 4;
    const float* A    = g_adj  + (size_t)b * NSQ;
    float*       xeff = g_xeff + (size_t)b * N_ * 384;
    const float* sums = (sel ? g_rowsum : g_colsum) + b * N_;
    const int outOff  = 128 + sel * 128;
    const int rowBase = blockIdx.y * 64;

    auto epi = [&](int row, int col, float v0, float v1, float v2, float v3) {
        float inv0 = 1.f / (sums[row]     + 1.f);
        float inv1 = 1.f / (sums[row + 8] + 1.f);
        float2 x0 = *reinterpret_cast<const float2*>(xeff + (size_t)row       * 384 + col);
        float2 x1 = *reinterpret_cast<const float2*>(xeff + (size_t)(row + 8) * 384 + col);
        float2 o0 = make_float2((v0 + x0.x) * inv0, (v1 + x0.y) * inv0);
        float2 o1 = make_float2((v2 + x1.x) * inv1, (v3 + x1.y) * inv1);
        *reinterpret_cast<float2*>(xeff + (size_t)row       * 384 + outOff + col) = o0;
        *reinterpret_cast<float2*>(xeff + (size_t)(row + 8) * 384 + outOff + col) = o1;
    };

    if (sel == 0)
        mma_pipe<64, 128, 2, 4, false>(A, xeff, N_, N_, 384, rowBase, sbuf, epi);
    else
        mma_pipe<64, 128, 2, 4, true >(A, xeff, N_, N_, 384, rowBase, sbuf, epi);
}

// ---------------------------------------------------------------------------
// K4b: gate projection + fused activation epilogue.
// val = xeff @ w1t (interleaved r/u cols). col even -> r, col odd -> u.
// writes u -> g_u, r*h -> xeff cols 64..127 (own rows only).
// ---------------------------------------------------------------------------
__global__ __launch_bounds__(256, 2)
void k4b_gate(const float* __restrict__ hx)
{
    __shared__ __align__(16) char sbuf[SB_BN128];
    const int rowBase = blockIdx.y * 64;

    auto epi = [&](int row, int col, float v0, float v1, float v2, float v3) {
        int o = col >> 1;
        float b_r = g_b1[col], b_u = g_b1[col + 1];
        float r0 = 1.f / (1.f + __expf(-(v0 + b_r)));
        float u0 = 1.f / (1.f + __expf(-(v1 + b_u)));
        float r1 = 1.f / (1.f + __expf(-(v2 + b_r)));
        float u1 = 1.f / (1.f + __expf(-(v3 + b_u)));
        g_u[(size_t)row * 64 + o]            = u0;
        g_u[(size_t)(row + 8) * 64 + o]      = u1;
        g_xeff[(size_t)row * 384 + 64 + o]       = r0 * hx[(size_t)row * 64 + o];
        g_xeff[(size_t)(row + 8) * 384 + 64 + o] = r1 * hx[(size_t)(row + 8) * 64 + o];
    };

    mma_pipe<64, 128, 2, 4, false>(g_xeff, g_w1t, 384, 384, 128, rowBase, sbuf, epi);
}

// ---------------------------------------------------------------------------
// K6: pass-2 SpMM pair over rh (xeff cols 64..127).
// sel0 -> Q0 into cols 192..255 (colsum), sel1 -> Q1 into cols 320..383 (rowsum).
// ---------------------------------------------------------------------------
__global__ __launch_bounds__(256, 2)
void k6_spmm()
{
    __shared__ __align__(16) char sbuf[SB_BN64];
    int z   = blockIdx.z;
    int b   = z & 15;
    int sel = z >> 4;
    const float* A    = g_adj  + (size_t)b * NSQ;
    float*       xeff = g_xeff + (size_t)b * N_ * 384;
    const float* sums = (sel ? g_rowsum : g_colsum) + b * N_;
    const int outOff  = 192 + sel * 128;
    const int rowBase = blockIdx.y * 64;

    auto epi = [&](int row, int col, float v0, float v1, float v2, float v3) {
        float inv0 = 1.f / (sums[row]     + 1.f);
        float inv1 = 1.f / (sums[row + 8] + 1.f);
        float2 x0 = *reinterpret_cast<const float2*>(xeff + (size_t)row       * 384 + 64 + col);
        float2 x1 = *reinterpret_cast<const float2*>(xeff + (size_t)(row + 8) * 384 + 64 + col);
        float2 o0 = make_float2((v0 + x0.x) * inv0, (v1 + x0.y) * inv0);
        float2 o1 = make_float2((v2 + x1.x) * inv1, (v3 + x1.y) * inv1);
        *reinterpret_cast<float2*>(xeff + (size_t)row       * 384 + outOff + col) = o0;
        *reinterpret_cast<float2*>(xeff + (size_t)(row + 8) * 384 + outOff + col) = o1;
    };

    if (sel == 0)
        mma_pipe<64, 64, 2, 4, false>(A, xeff + 64, N_, N_, 384, rowBase, sbuf, epi);
    else
        mma_pipe<64, 64, 2, 4, true >(A, xeff + 64, N_, N_, 384, rowBase, sbuf, epi);
}

// ---------------------------------------------------------------------------
// K8: candidate projection + fused final GRU epilogue.
// c = tanh(xeff @ w2t + b2); out = u*h + (1-u)*c
// ---------------------------------------------------------------------------
__global__ __launch_bounds__(256, 2)
void k8_cand(const float* __restrict__ hx, float* __restrict__ out)
{
    __shared__ __align__(16) char sbuf[SB_BN64];
    const int rowBase = blockIdx.y * 64;

    auto epi = [&](int row, int col, float v0, float v1, float v2, float v3) {
        float b0v = g_b2[col], b1v = g_b2[col + 1];
        float c00 = tanhf(v0 + b0v), c01 = tanhf(v1 + b1v);
        float c10 = tanhf(v2 + b0v), c11 = tanhf(v3 + b1v);
        size_t i0 = (size_t)row * 64 + col;
        size_t i1 = (size_t)(row + 8) * 64 + col;
        float2 u0 = *reinterpret_cast<const float2*>(g_u + i0);
        float2 u1 = *reinterpret_cast<const float2*>(g_u + i1);
        float2 h0 = *reinterpret_cast<const float2*>(hx + i0);
        float2 h1 = *reinterpret_cast<const float2*>(hx + i1);
        float2 o0 = make_float2(u0.x * h0.x + (1.f - u0.x) * c00,
                                u0.y * h0.y + (1.f - u0.y) * c01);
        float2 o1 = make_float2(u1.x * h1.x + (1.f - u1.x) * c10,
                                u1.y * h1.y + (1.f - u1.y) * c11);
        *reinterpret_cast<float2*>(out + i0) = o0;
        *reinterpret_cast<float2*>(out + i1) = o1;
    };

    mma_pipe<64, 64, 2, 4, false>(g_xeff, g_w2t, 384, 384, 64, rowBase, sbuf, epi);
}

// ---------------------------------------------------------------------------
// Launch: kernel launches only (graph-capture safe)
// ---------------------------------------------------------------------------
extern "C" void kernel_launch(void* const* d_in, const int* in_sizes, int n_in,
                              void* d_out, int out_size)
{
    const float* logits = (const float*)d_in[0];
    const float* unoise = (const float*)d_in[1];
    const float* inputs = (const float*)d_in[2];
    const float* hx     = (const float*)d_in[3];
    const float* W0     = (const float*)d_in[4];
    const float* b0     = (const float*)d_in[5];
    const float* W1     = (const float*)d_in[6];
    const float* b1     = (const float*)d_in[7];
    const float* Wc0    = (const float*)d_in[8];
    const float* bc0    = (const float*)d_in[9];
    const float* Wc1    = (const float*)d_in[10];
    const float* bc1    = (const float*)d_in[11];
    float* out          = (float*)d_out;

    k0_prep<<<128, 256>>>(W0, b0, W1, b1, Wc0, bc0, Wc1, bc1);

    k1_gumbel<<<dim3(N_/32, N_/32, B_), dim3(32, 8)>>>(logits, unoise);

    k2_xcat<<<(NB * 128 + 255) / 256, 256>>>(inputs, hx);

    k3_spmm<<<dim3(1, N_/64, 2 * B_), 256>>>();

    k4b_gate<<<dim3(1, NB/64, 1), 256>>>(hx);

    k6_spmm<<<dim3(1, N_/64, 2 * B_), 256>>>();

    k8_cand<<<dim3(1, NB/64, 1), 256>>>(hx, out);
}

// round 9
// speedup vs baseline: 1.1607x; 1.1607x over previous
#include <cuda_runtime.h>
#include <cstdint>

// Problem constants
static constexpr int   B_   = 16;
static constexpr int   N_   = 1024;
static constexpr float EPS_ = 1e-10f;
static constexpr int   NSQ  = N_ * N_;        // 1048576
static constexpr int   NB   = B_ * N_;        // 16384 nodes total

// ---------------------------------------------------------------------------
// Scratch (device globals; allocation is forbidden)
// xeff layout per node (384 floats):
//   [  0.. 63] xin
//   [ 64..127] h        (pass 1)  ->  r*h   (overwritten by k4b epilogue)
//   [128..191] P0x = ((adj @x)+x)_xin * invc
//   [192..255] P0h (pass 1)       ->  Q0 = ((adj @rh)+rh)*invc (k6 epilogue)
//   [256..319] P1x = ((adjT@x)+x)_xin * invr
//   [320..383] P1h (pass 1)       ->  Q1 = ((adjT@rh)+rh)*invr (k6 epilogue)
// ---------------------------------------------------------------------------
__device__ float g_adj  [B_ * NSQ];          // 64 MB  adj[b,i,j]
__device__ float g_rowsum[NB];               // sum_j adj[i,j]
__device__ float g_colsum[NB];               // sum_i adj[i,j]
__device__ float g_xeff [NB * 384];
__device__ float g_u    [NB * 64];           // update gate
__device__ float g_w1t  [384 * 128];         // gate weights, (k,o'), o' interleaved r/u
__device__ float g_w2t  [384 * 64];          // candidate weights, (k,o)
__device__ float g_b1   [128];               // interleaved r/u bias
__device__ float g_b2   [64];

// ---------------------------------------------------------------------------
// cp.async helpers
// ---------------------------------------------------------------------------
__device__ __forceinline__ void cp_async16(void* smem_dst, const void* gsrc)
{
    uint32_t s = (uint32_t)__cvta_generic_to_shared(smem_dst);
    asm volatile("cp.async.cg.shared.global [%0], [%1], 16;\n" :: "r"(s), "l"(gsrc));
}
__device__ __forceinline__ void cp_commit() { asm volatile("cp.async.commit_group;\n"); }
__device__ __forceinline__ void cp_wait1()  { asm volatile("cp.async.wait_group 1;\n"); }
__device__ __forceinline__ void cp_wait0()  { asm volatile("cp.async.wait_group 0;\n"); }

__device__ __forceinline__ void mma_m16n8k8(float c[4],
                                            uint32_t a0, uint32_t a1, uint32_t a2, uint32_t a3,
                                            uint32_t b0, uint32_t b1)
{
    asm volatile("mma.sync.aligned.m16n8k8.row.col.f32.tf32.tf32.f32 "
                 "{%0,%1,%2,%3}, {%4,%5,%6,%7}, {%8,%9}, {%0,%1,%2,%3};\n"
                 : "+f"(c[0]), "+f"(c[1]), "+f"(c[2]), "+f"(c[3])
                 : "r"(a0), "r"(a1), "r"(a2), "r"(a3), "r"(b0), "r"(b1));
}

// ---------------------------------------------------------------------------
// Pipelined TF32 MMA core (double-buffered cp.async, BK=16).  (R6 config —
// the BM=64 split in R7 regressed: halved A-tile reuse outweighed the issue
// gain.)
//   AKM=false: A row-major (element (m,k) at A[m*ldA+k]); smem A [BM][20]
//   AKM=true : A K-major   (element (m,k) at A[k*ldA+m]); smem A [16][BM+8]
// Raw fp32 bits feed the TF32 MMA (hardware truncates to 19 bits).
// Epi(rowGlobal, colLocal, v0, v1, v2, v3): values at (row,col),(row,col+1),
// (row+8,col),(row+8,col+1); col is always even.
// ---------------------------------------------------------------------------
template<int BM, int BN, int WARPS_M, int WARPS_N, bool AKM, class Epi>
__device__ __forceinline__ void mma_pipe(const float* __restrict__ A,
                                         const float* __restrict__ X,
                                         int Kd, int ldA, int ldX,
                                         int rowBase, char* sbuf, Epi epi)
{
    constexpr int BK      = 16;
    constexpr int THREADS = WARPS_M * WARPS_N * 32;
    constexpr int WM = BM / WARPS_M;
    constexpr int WN = BN / WARPS_N;
    constexpr int MI = WM / 16;
    constexpr int NI = WN / 8;
    constexpr int A_ST_RM = BK + 4;        // 20 floats
    constexpr int A_ST_KM = BM + 8;        // 136 floats
    constexpr int A_FLOATS = AKM ? BK * A_ST_KM : BM * A_ST_RM;
    constexpr int B_ST = BN + 8;
    constexpr int B_FLOATS = BK * B_ST;

    float* As0 = (float*)sbuf;
    float* As1 = As0 + A_FLOATS;
    float* Bs0 = As1 + A_FLOATS;
    float* Bs1 = Bs0 + B_FLOATS;

    const int tid  = threadIdx.x;
    const int lane = tid & 31;
    const int w    = tid >> 5;
    const int wm   = w / WARPS_N;
    const int wn   = w % WARPS_N;
    const int grp  = lane >> 2;     // 0..7
    const int qid  = lane & 3;      // 0..3

    float acc[MI][NI][4];
#pragma unroll
    for (int mi = 0; mi < MI; ++mi)
#pragma unroll
        for (int ni = 0; ni < NI; ++ni)
#pragma unroll
            for (int r = 0; r < 4; ++r) acc[mi][ni][r] = 0.f;

    auto load_stage = [&](int s, int k0) {
        float* As = s ? As1 : As0;
        float* Bs = s ? Bs1 : Bs0;
        if (AKM) {
#pragma unroll
            for (int i = tid; i < BK * (BM / 4); i += THREADS) {
                int kr = i / (BM / 4), mq = i % (BM / 4);
                cp_async16(As + kr * A_ST_KM + mq * 4,
                           A + (size_t)(k0 + kr) * ldA + rowBase + mq * 4);
            }
        } else {
#pragma unroll
            for (int i = tid; i < BM * (BK / 4); i += THREADS) {
                int m = i / (BK / 4), kq = i % (BK / 4);
                cp_async16(As + m * A_ST_RM + kq * 4,
                           A + (size_t)(rowBase + m) * ldA + k0 + kq * 4);
            }
        }
#pragma unroll
        for (int i = tid; i < BK * (BN / 4); i += THREADS) {
            int kr = i / (BN / 4), cq = i % (BN / 4);
            cp_async16(Bs + kr * B_ST + cq * 4,
                       X + (size_t)(k0 + kr) * ldX + cq * 4);
        }
    };

    load_stage(0, 0);
    cp_commit();

    const int nIter = Kd / BK;
    for (int it = 0; it < nIter; ++it) {
        const int cur = it & 1;
        if (it + 1 < nIter) {
            load_stage(cur ^ 1, (it + 1) * BK);
            cp_commit();
            cp_wait1();
        } else {
            cp_wait0();
        }
        __syncthreads();

        const float* As = cur ? As1 : As0;
        const float* Bs = cur ? Bs1 : Bs0;

#pragma unroll
        for (int ks = 0; ks < BK / 8; ++ks) {
            const int kb = ks * 8 + qid;
            uint32_t afr[MI][4];
            uint32_t bfr[NI][2];
#pragma unroll
            for (int mi = 0; mi < MI; ++mi) {
                int row = wm * WM + mi * 16 + grp;
                if (AKM) {
                    afr[mi][0] = __float_as_uint(As[(kb    ) * A_ST_KM + row    ]);
                    afr[mi][1] = __float_as_uint(As[(kb    ) * A_ST_KM + row + 8]);
                    afr[mi][2] = __float_as_uint(As[(kb + 4) * A_ST_KM + row    ]);
                    afr[mi][3] = __float_as_uint(As[(kb + 4) * A_ST_KM + row + 8]);
                } else {
                    afr[mi][0] = __float_as_uint(As[(row    ) * A_ST_RM + kb    ]);
                    afr[mi][1] = __float_as_uint(As[(row + 8) * A_ST_RM + kb    ]);
                    afr[mi][2] = __float_as_uint(As[(row    ) * A_ST_RM + kb + 4]);
                    afr[mi][3] = __float_as_uint(As[(row + 8) * A_ST_RM + kb + 4]);
                }
            }
#pragma unroll
            for (int ni = 0; ni < NI; ++ni) {
                int col = wn * WN + ni * 8 + grp;
                bfr[ni][0] = __float_as_uint(Bs[(kb    ) * B_ST + col]);
                bfr[ni][1] = __float_as_uint(Bs[(kb + 4) * B_ST + col]);
            }
#pragma unroll
            for (int mi = 0; mi < MI; ++mi)
#pragma unroll
                for (int ni = 0; ni < NI; ++ni)
                    mma_m16n8k8(acc[mi][ni],
                                afr[mi][0], afr[mi][1], afr[mi][2], afr[mi][3],
                                bfr[ni][0], bfr[ni][1]);
        }
        __syncthreads();
    }

#pragma unroll
    for (int mi = 0; mi < MI; ++mi)
#pragma unroll
        for (int ni = 0; ni < NI; ++ni) {
            int row = rowBase + wm * WM + mi * 16 + grp;
            int col = wn * WN + ni * 8 + 2 * qid;
            epi(row, col, acc[mi][ni][0], acc[mi][ni][1], acc[mi][ni][2], acc[mi][ni][3]);
        }
}

// ---------------------------------------------------------------------------
// K0: fold weights. Reference's diffusion appends `prev` twice (A^2 x unused)
// so steps 1+2 share Ax -> pre-sum those weight columns. w1t output columns
// interleaved: o'=2o -> r-channel o, o'=2o+1 -> u-channel o (orig row o+64).
// ---------------------------------------------------------------------------
__global__ void k0_prep(const float* __restrict__ W0, const float* __restrict__ b0,
                        const float* __restrict__ W1, const float* __restrict__ b1,
                        const float* __restrict__ Wc0, const float* __restrict__ bc0,
                        const float* __restrict__ Wc1, const float* __restrict__ bc1)
{
    int idx    = blockIdx.x * blockDim.x + threadIdx.x;
    int stride = gridDim.x * blockDim.x;

    for (int i = idx; i < 384 * 128; i += stride) {
        int k = i / 128, o = i % 128;
        int orig = (o & 1) ? (o >> 1) + 64 : (o >> 1);     // interleave r/u
        float v;
        if (k < 128)       { int c = k;        v = W0[orig*384 + 3*c]     + W1[orig*384 + 3*c];     }
        else if (k < 256)  { int c = k - 128;  v = W0[orig*384 + 3*c + 1] + W0[orig*384 + 3*c + 2]; }
        else               { int c = k - 256;  v = W1[orig*384 + 3*c + 1] + W1[orig*384 + 3*c + 2]; }
        g_w1t[i] = v;
    }
    for (int i = idx; i < 384 * 64; i += stride) {
        int k = i / 64, o = i % 64;
        float v;
        if (k < 128)       { int c = k;        v = Wc0[o*384 + 3*c]     + Wc1[o*384 + 3*c];     }
        else if (k < 256)  { int c = k - 128;  v = Wc0[o*384 + 3*c + 1] + Wc0[o*384 + 3*c + 2]; }
        else               { int c = k - 256;  v = Wc1[o*384 + 3*c + 1] + Wc1[o*384 + 3*c + 2]; }
        g_w2t[i] = v;
    }
    for (int i = idx; i < 128; i += stride) {
        int orig = (i & 1) ? (i >> 1) + 64 : (i >> 1);
        g_b1[i] = b0[orig] + b1[orig];
    }
    for (int i = idx; i < 64;  i += stride) g_b2[i] = bc0[i] + bc1[i];
    for (int i = idx; i < NB;  i += stride) { g_rowsum[i] = 0.f; g_colsum[i] = 0.f; }
}

// ---------------------------------------------------------------------------
// K1: Gumbel-softmax adjacency + row/col sums (fused), MUFU-reduced form.
// Reference: a = softmax((l+gumbel(u))/tau)[0], gumbel(u) = -log(EPS-log(u+EPS))
// Algebra (tau=0.5):
//   a = 1/(1 + exp(2*(l1-l0)) * (g0/g1)^2) = g1^2 / (g1^2 + E*g0^2)
// with g_i = EPS - log(u_i+EPS), E = exp(2*(l1-l0)).
// 4 MUFU (2 log, 1 exp, 1 rcp) vs 6 in the naive form.
// ---------------------------------------------------------------------------
__global__ void k1_gumbel(const float* __restrict__ logits,
                          const float* __restrict__ unoise)
{
    __shared__ float scol[8][32];

    const int b  = blockIdx.z;
    const int i0 = blockIdx.y * 32;
    const int j0 = blockIdx.x * 32;
    const int tx = threadIdx.x;
    const int ty = threadIdx.y;

    const float2* lg = reinterpret_cast<const float2*>(logits) + (size_t)b * NSQ;
    const float2* un = reinterpret_cast<const float2*>(unoise) + (size_t)b * NSQ;

    float vals[4];
#pragma unroll
    for (int sI = 0; sI < 4; ++sI) {
        int row  = ty + 8 * sI;
        size_t e = (size_t)(i0 + row) * N_ + (j0 + tx);
        float2 l = lg[e];
        float2 u = un[e];
        float g0 = EPS_ - __logf(u.x + EPS_);          // > 0
        float g1 = EPS_ - __logf(u.y + EPS_);          // > 0
        float E  = __expf(2.0f * (l.y - l.x));         // exp(2*dl)
        float g0s = g0 * g0;
        float g1s = g1 * g1;
        float a  = __fdividef(g1s, fmaf(E, g0s, g1s)); // g1^2/(g1^2+E*g0^2)
        vals[sI] = a;
        g_adj[(size_t)b * NSQ + e] = a;
    }

#pragma unroll
    for (int sI = 0; sI < 4; ++sI) {
        float v = vals[sI];
#pragma unroll
        for (int o = 16; o > 0; o >>= 1) v += __shfl_down_sync(0xffffffffu, v, o);
        if (tx == 0) atomicAdd(&g_rowsum[b * N_ + i0 + ty + 8 * sI], v);
    }

    scol[ty][tx] = vals[0] + vals[1] + vals[2] + vals[3];
    __syncthreads();
    if (ty == 0) {
        float t2 = 0.f;
#pragma unroll
        for (int w = 0; w < 8; ++w) t2 += scol[w][tx];
        atomicAdd(&g_colsum[b * N_ + j0 + tx], t2);
    }
}

// ---------------------------------------------------------------------------
// K2: write xin -> xeff[0..63], h -> xeff[64..127]
// ---------------------------------------------------------------------------
__global__ void k2_xcat(const float* __restrict__ inp, const float* __restrict__ hx)
{
    size_t idx = (size_t)blockIdx.x * blockDim.x + threadIdx.x;
    if (idx >= (size_t)NB * 128) return;
    size_t node = idx >> 7;
    int c = (int)(idx & 127);
    float v = (c < 64) ? inp[node * 64 + c] : hx[node * 64 + (c - 64)];
    g_xeff[node * 384 + c] = v;
}

// ---------------------------------------------------------------------------
// Shared buffer sizes (bytes), BM=128 (R6 config)
// ---------------------------------------------------------------------------
static constexpr int SB_BN128 = (128*20*2 + 16*136*2) * 4;   // 37888 B
static constexpr int SB_BN64  = (128*20*2 + 16*72*2)  * 4;   // 29696 B

// ---------------------------------------------------------------------------
// K3: pass-1 SpMM pair. sel0: p0 = adj@xcat, scaled by 1/(colsum+1), into
// xeff cols 128..255. sel1: p1 = adjT@xcat, 1/(rowsum+1), cols 256..383.
// Epilogue adds the identity term (x) before scaling.
// ---------------------------------------------------------------------------
__global__ __launch_bounds__(256, 2)
void k3_spmm()
{
    __shared__ __align__(16) char sbuf[SB_BN128];
    int z   = blockIdx.z;
    int b   = z & 15;
    int sel = z >> 4;
    const float* A    = g_adj  + (size_t)b * NSQ;
    float*       xeff = g_xeff + (size_t)b * N_ * 384;
    const float* sums = (sel ? g_rowsum : g_colsum) + b * N_;
    const int outOff  = 128 + sel * 128;
    const int rowBase = blockIdx.y * 128;

    auto epi = [&](int row, int col, float v0, float v1, float v2, float v3) {
        float inv0 = 1.f / (sums[row]     + 1.f);
        float inv1 = 1.f / (sums[row + 8] + 1.f);
        float2 x0 = *reinterpret_cast<const float2*>(xeff + (size_t)row       * 384 + col);
        float2 x1 = *reinterpret_cast<const float2*>(xeff + (size_t)(row + 8) * 384 + col);
        float2 o0 = make_float2((v0 + x0.x) * inv0, (v1 + x0.y) * inv0);
        float2 o1 = make_float2((v2 + x1.x) * inv1, (v3 + x1.y) * inv1);
        *reinterpret_cast<float2*>(xeff + (size_t)row       * 384 + outOff + col) = o0;
        *reinterpret_cast<float2*>(xeff + (size_t)(row + 8) * 384 + outOff + col) = o1;
    };

    if (sel == 0)
        mma_pipe<128, 128, 2, 4, false>(A, xeff, N_, N_, 384, rowBase, sbuf, epi);
    else
        mma_pipe<128, 128, 2, 4, true >(A, xeff, N_, N_, 384, rowBase, sbuf, epi);
}

// ---------------------------------------------------------------------------
// K4b: gate projection + fused activation epilogue.
// val = xeff @ w1t (interleaved r/u cols). col even -> r, col odd -> u.
// writes u -> g_u, r*h -> xeff cols 64..127 (own rows only).
// ---------------------------------------------------------------------------
__global__ __launch_bounds__(256, 2)
void k4b_gate(const float* __restrict__ hx)
{
    __shared__ __align__(16) char sbuf[SB_BN128];
    const int rowBase = blockIdx.y * 128;

    auto epi = [&](int row, int col, float v0, float v1, float v2, float v3) {
        int o = col >> 1;
        float b_r = g_b1[col], b_u = g_b1[col + 1];
        float r0 = 1.f / (1.f + __expf(-(v0 + b_r)));
        float u0 = 1.f / (1.f + __expf(-(v1 + b_u)));
        float r1 = 1.f / (1.f + __expf(-(v2 + b_r)));
        float u1 = 1.f / (1.f + __expf(-(v3 + b_u)));
        g_u[(size_t)row * 64 + o]            = u0;
        g_u[(size_t)(row + 8) * 64 + o]      = u1;
        g_xeff[(size_t)row * 384 + 64 + o]       = r0 * hx[(size_t)row * 64 + o];
        g_xeff[(size_t)(row + 8) * 384 + 64 + o] = r1 * hx[(size_t)(row + 8) * 64 + o];
    };

    mma_pipe<128, 128, 2, 4, false>(g_xeff, g_w1t, 384, 384, 128, rowBase, sbuf, epi);
}

// ---------------------------------------------------------------------------
// K6: pass-2 SpMM pair over rh (xeff cols 64..127).
// sel0 -> Q0 into cols 192..255 (colsum), sel1 -> Q1 into cols 320..383 (rowsum).
// ---------------------------------------------------------------------------
__global__ __launch_bounds__(256, 2)
void k6_spmm()
{
    __shared__ __align__(16) char sbuf[SB_BN64];
    int z   = blockIdx.z;
    int b   = z & 15;
    int sel = z >> 4;
    const float* A    = g_adj  + (size_t)b * NSQ;
    float*       xeff = g_xeff + (size_t)b * N_ * 384;
    const float* sums = (sel ? g_rowsum : g_colsum) + b * N_;
    const int outOff  = 192 + sel * 128;
    const int rowBase = blockIdx.y * 128;

    auto epi = [&](int row, int col, float v0, float v1, float v2, float v3) {
        float inv0 = 1.f / (sums[row]     + 1.f);
        float inv1 = 1.f / (sums[row + 8] + 1.f);
        float2 x0 = *reinterpret_cast<const float2*>(xeff + (size_t)row       * 384 + 64 + col);
        float2 x1 = *reinterpret_cast<const float2*>(xeff + (size_t)(row + 8) * 384 + 64 + col);
        float2 o0 = make_float2((v0 + x0.x) * inv0, (v1 + x0.y) * inv0);
        float2 o1 = make_float2((v2 + x1.x) * inv1, (v3 + x1.y) * inv1);
        *reinterpret_cast<float2*>(xeff + (size_t)row       * 384 + outOff + col) = o0;
        *reinterpret_cast<float2*>(xeff + (size_t)(row + 8) * 384 + outOff + col) = o1;
    };

    if (sel == 0)
        mma_pipe<128, 64, 4, 2, false>(A, xeff + 64, N_, N_, 384, rowBase, sbuf, epi);
    else
        mma_pipe<128, 64, 4, 2, true >(A, xeff + 64, N_, N_, 384, rowBase, sbuf, epi);
}

// ---------------------------------------------------------------------------
// K8: candidate projection + fused final GRU epilogue.
// c = tanh(xeff @ w2t + b2); out = u*h + (1-u)*c
// ---------------------------------------------------------------------------
__global__ __launch_bounds__(256, 2)
void k8_cand(const float* __restrict__ hx, float* __restrict__ out)
{
    __shared__ __align__(16) char sbuf[SB_BN64];
    const int rowBase = blockIdx.y * 128;

    auto epi = [&](int row, int col, float v0, float v1, float v2, float v3) {
        float b0v = g_b2[col], b1v = g_b2[col + 1];
        float c00 = tanhf(v0 + b0v), c01 = tanhf(v1 + b1v);
        float c10 = tanhf(v2 + b0v), c11 = tanhf(v3 + b1v);
        size_t i0 = (size_t)row * 64 + col;
        size_t i1 = (size_t)(row + 8) * 64 + col;
        float2 u0 = *reinterpret_cast<const float2*>(g_u + i0);
        float2 u1 = *reinterpret_cast<const float2*>(g_u + i1);
        float2 h0 = *reinterpret_cast<const float2*>(hx + i0);
        float2 h1 = *reinterpret_cast<const float2*>(hx + i1);
        float2 o0 = make_float2(u0.x * h0.x + (1.f - u0.x) * c00,
                                u0.y * h0.y + (1.f - u0.y) * c01);
        float2 o1 = make_float2(u1.x * h1.x + (1.f - u1.x) * c10,
                                u1.y * h1.y + (1.f - u1.y) * c11);
        *reinterpret_cast<float2*>(out + i0) = o0;
        *reinterpret_cast<float2*>(out + i1) = o1;
    };

    mma_pipe<128, 64, 4, 2, false>(g_xeff, g_w2t, 384, 384, 64, rowBase, sbuf, epi);
}

// ---------------------------------------------------------------------------
// Launch: kernel launches only (graph-capture safe)
// ---------------------------------------------------------------------------
extern "C" void kernel_launch(void* const* d_in, const int* in_sizes, int n_in,
                              void* d_out, int out_size)
{
    const float* logits = (const float*)d_in[0];
    const float* unoise = (const float*)d_in[1];
    const float* inputs = (const float*)d_in[2];
    const float* hx     = (const float*)d_in[3];
    const float* W0     = (const float*)d_in[4];
    const float* b0     = (const float*)d_in[5];
    const float* W1     = (const float*)d_in[6];
    const float* b1     = (const float*)d_in[7];
    const float* Wc0    = (const float*)d_in[8];
    const float* bc0    = (const float*)d_in[9];
    const float* Wc1    = (const float*)d_in[10];
    const float* bc1    = (const float*)d_in[11];
    float* out          = (float*)d_out;

    k0_prep<<<128, 256>>>(W0, b0, W1, b1, Wc0, bc0, Wc1, bc1);

    k1_gumbel<<<dim3(N_/32, N_/32, B_), dim3(32, 8)>>>(logits, unoise);

    k2_xcat<<<(NB * 128 + 255) / 256, 256>>>(inputs, hx);

    k3_spmm<<<dim3(1, N_/128, 2 * B_), 256>>>();

    k4b_gate<<<dim3(1, NB/128, 1), 256>>>(hx);

    k6_spmm<<<dim3(1, N_/128, 2 * B_), 256>>>();

    k8_cand<<<dim3(1, NB/128, 1), 256>>>(hx, out);
}

// round 10
// speedup vs baseline: 1.3531x; 1.1657x over previous
#include <cuda_runtime.h>
#include <cuda_fp16.h>
#include <cstdint>

// Problem constants
static constexpr int   B_   = 16;
static constexpr int   N_   = 1024;
static constexpr float EPS_ = 1e-10f;
static constexpr int   NSQ  = N_ * N_;        // 1048576
static constexpr int   NB   = B_ * N_;        // 16384 nodes total

// ---------------------------------------------------------------------------
// Scratch (device globals; allocation is forbidden)
// xeff layout per node (384 floats):
//   [  0.. 63] xin
//   [ 64..127] h        (pass 1)  ->  r*h   (overwritten by k4b epilogue)
//   [128..191] P0x = ((adj @x)+x)_xin * invc
//   [192..255] P0h (pass 1)       ->  Q0 = ((adj @rh)+rh)*invc (k6 epilogue)
//   [256..319] P1x = ((adjT@x)+x)_xin * invr
//   [320..383] P1h (pass 1)       ->  Q1 = ((adjT@rh)+rh)*invr (k6 epilogue)
// ---------------------------------------------------------------------------
__device__ __half g_adj16[B_ * NSQ];         // 32 MB  adj[b,i,j] fp16 (MMA operand)
__device__ float  g_rowsum[NB];              // sum_j adj[i,j] (fp32, pre-rounding)
__device__ float  g_colsum[NB];              // sum_i adj[i,j]
__device__ float  g_xeff [NB * 384];
__device__ __half g_x16  [NB * 128];         // fp16 copy of [xin|h]  (SpMM B operand)
__device__ __half g_rh16 [NB * 64];          // fp16 copy of r*h      (SpMM B operand)
__device__ float  g_u    [NB * 64];          // update gate
__device__ float  g_w1t  [384 * 128];        // gate weights, (k,o'), o' interleaved r/u
__device__ float  g_w2t  [384 * 64];         // candidate weights, (k,o)
__device__ float  g_b1   [128];              // interleaved r/u bias
__device__ float  g_b2   [64];

// ---------------------------------------------------------------------------
// cp.async helpers
// ---------------------------------------------------------------------------
__device__ __forceinline__ void cp_async16(void* smem_dst, const void* gsrc)
{
    uint32_t s = (uint32_t)__cvta_generic_to_shared(smem_dst);
    asm volatile("cp.async.cg.shared.global [%0], [%1], 16;\n" :: "r"(s), "l"(gsrc));
}
__device__ __forceinline__ void cp_commit() { asm volatile("cp.async.commit_group;\n"); }
__device__ __forceinline__ void cp_wait1()  { asm volatile("cp.async.wait_group 1;\n"); }
__device__ __forceinline__ void cp_wait0()  { asm volatile("cp.async.wait_group 0;\n"); }

__device__ __forceinline__ void mma_m16n8k8(float c[4],
                                            uint32_t a0, uint32_t a1, uint32_t a2, uint32_t a3,
                                            uint32_t b0, uint32_t b1)
{
    asm volatile("mma.sync.aligned.m16n8k8.row.col.f32.tf32.tf32.f32 "
                 "{%0,%1,%2,%3}, {%4,%5,%6,%7}, {%8,%9}, {%0,%1,%2,%3};\n"
                 : "+f"(c[0]), "+f"(c[1]), "+f"(c[2]), "+f"(c[3])
                 : "r"(a0), "r"(a1), "r"(a2), "r"(a3), "r"(b0), "r"(b1));
}

__device__ __forceinline__ void mma_m16n8k16h(float c[4],
                                              uint32_t a0, uint32_t a1, uint32_t a2, uint32_t a3,
                                              uint32_t b0, uint32_t b1)
{
    asm volatile("mma.sync.aligned.m16n8k16.row.col.f32.f16.f16.f32 "
                 "{%0,%1,%2,%3}, {%4,%5,%6,%7}, {%8,%9}, {%0,%1,%2,%3};\n"
                 : "+f"(c[0]), "+f"(c[1]), "+f"(c[2]), "+f"(c[3])
                 : "r"(a0), "r"(a1), "r"(a2), "r"(a3), "r"(b0), "r"(b1));
}

__device__ __forceinline__ uint32_t pack2(const __half* p0, const __half* p1)
{
    unsigned short lo = *(const unsigned short*)p0;
    unsigned short hi = *(const unsigned short*)p1;
    return (uint32_t)lo | ((uint32_t)hi << 16);
}

// ---------------------------------------------------------------------------
// FP16 pipelined MMA core (m16n8k16, BK=32, double-buffered cp.async).
// Used for the SpMMs: adj is fp16 (same 10-bit mantissa as tf32, values in
// (0,1)), halving MMA count, fragment loads, K-iterations and A HBM traffic.
//   AKM=false: A row-major  (element (m,k) at A[m*ldA+k]); smem [BM][40] halves
//   AKM=true : A K-major    (element (m,k) at A[k*ldA+m]); smem [32][BM+8]
// Epi identical contract to the tf32 core.
// ---------------------------------------------------------------------------
template<int BM, int BN, int WARPS_M, int WARPS_N, bool AKM, class Epi>
__device__ __forceinline__ void mma_pipe_h(const __half* __restrict__ A,
                                           const __half* __restrict__ X,
                                           int Kd, int ldA, int ldX,
                                           int rowBase, char* sbuf, Epi epi)
{
    constexpr int BK      = 32;
    constexpr int THREADS = WARPS_M * WARPS_N * 32;
    constexpr int WM = BM / WARPS_M;
    constexpr int WN = BN / WARPS_N;
    constexpr int MI = WM / 16;
    constexpr int NI = WN / 8;
    constexpr int LDA_RM = BK + 8;          // 40 halves (word stride 20: conflict-free)
    constexpr int LDM_KM = BM + 8;          // 136 halves
    constexpr int A_HALVES = AKM ? BK * LDM_KM : BM * LDA_RM;
    constexpr int LDB = BN + 8;
    constexpr int B_HALVES = BK * LDB;

    __half* As0 = (__half*)sbuf;
    __half* As1 = As0 + A_HALVES;
    __half* Bs0 = As1 + A_HALVES;
    __half* Bs1 = Bs0 + B_HALVES;

    const int tid  = threadIdx.x;
    const int lane = tid & 31;
    const int w    = tid >> 5;
    const int wm   = w / WARPS_N;
    const int wn   = w % WARPS_N;
    const int grp  = lane >> 2;     // 0..7
    const int qid  = lane & 3;      // 0..3

    float acc[MI][NI][4];
#pragma unroll
    for (int mi = 0; mi < MI; ++mi)
#pragma unroll
        for (int ni = 0; ni < NI; ++ni)
#pragma unroll
            for (int r = 0; r < 4; ++r) acc[mi][ni][r] = 0.f;

    auto load_stage = [&](int s, int k0) {
        __half* As = s ? As1 : As0;
        __half* Bs = s ? Bs1 : Bs0;
        if (AKM) {
#pragma unroll
            for (int i = tid; i < BK * (BM / 8); i += THREADS) {
                int kr = i / (BM / 8), mq = i % (BM / 8);
                cp_async16(As + kr * LDM_KM + mq * 8,
                           A + (size_t)(k0 + kr) * ldA + rowBase + mq * 8);
            }
        } else {
#pragma unroll
            for (int i = tid; i < BM * (BK / 8); i += THREADS) {
                int m = i / (BK / 8), kq = i % (BK / 8);
                cp_async16(As + m * LDA_RM + kq * 8,
                           A + (size_t)(rowBase + m) * ldA + k0 + kq * 8);
            }
        }
#pragma unroll
        for (int i = tid; i < BK * (BN / 8); i += THREADS) {
            int kr = i / (BN / 8), cq = i % (BN / 8);
            cp_async16(Bs + kr * LDB + cq * 8,
                       X + (size_t)(k0 + kr) * ldX + cq * 8);
        }
    };

    load_stage(0, 0);
    cp_commit();

    const int nIter = Kd / BK;
    for (int it = 0; it < nIter; ++it) {
        const int cur = it & 1;
        if (it + 1 < nIter) {
            load_stage(cur ^ 1, (it + 1) * BK);
            cp_commit();
            cp_wait1();
        } else {
            cp_wait0();
        }
        __syncthreads();

        const __half* As = cur ? As1 : As0;
        const __half* Bs = cur ? Bs1 : Bs0;

#pragma unroll
        for (int ks = 0; ks < 2; ++ks) {           // two K=16 steps per BK=32
            const int kh = ks * 16 + 2 * qid;
            uint32_t afr[MI][4];
            uint32_t bfr[NI][2];
#pragma unroll
            for (int mi = 0; mi < MI; ++mi) {
                int row = wm * WM + mi * 16 + grp;
                if (AKM) {
                    afr[mi][0] = pack2(&As[(kh    ) * LDM_KM + row    ], &As[(kh + 1) * LDM_KM + row    ]);
                    afr[mi][1] = pack2(&As[(kh    ) * LDM_KM + row + 8], &As[(kh + 1) * LDM_KM + row + 8]);
                    afr[mi][2] = pack2(&As[(kh + 8) * LDM_KM + row    ], &As[(kh + 9) * LDM_KM + row    ]);
                    afr[mi][3] = pack2(&As[(kh + 8) * LDM_KM + row + 8], &As[(kh + 9) * LDM_KM + row + 8]);
                } else {
                    afr[mi][0] = *(const uint32_t*)(As + (row    ) * LDA_RM + kh);
                    afr[mi][1] = *(const uint32_t*)(As + (row + 8) * LDA_RM + kh);
                    afr[mi][2] = *(const uint32_t*)(As + (row    ) * LDA_RM + kh + 8);
                    afr[mi][3] = *(const uint32_t*)(As + (row + 8) * LDA_RM + kh + 8);
                }
            }
#pragma unroll
            for (int ni = 0; ni < NI; ++ni) {
                int col = wn * WN + ni * 8 + grp;
                bfr[ni][0] = pack2(&Bs[(kh    ) * LDB + col], &Bs[(kh + 1) * LDB + col]);
                bfr[ni][1] = pack2(&Bs[(kh + 8) * LDB + col], &Bs[(kh + 9) * LDB + col]);
            }
#pragma unroll
            for (int mi = 0; mi < MI; ++mi)
#pragma unroll
                for (int ni = 0; ni < NI; ++ni)
                    mma_m16n8k16h(acc[mi][ni],
                                  afr[mi][0], afr[mi][1], afr[mi][2], afr[mi][3],
                                  bfr[ni][0], bfr[ni][1]);
        }
        __syncthreads();
    }

#pragma unroll
    for (int mi = 0; mi < MI; ++mi)
#pragma unroll
        for (int ni = 0; ni < NI; ++ni) {
            int row = rowBase + wm * WM + mi * 16 + grp;
            int col = wn * WN + ni * 8 + 2 * qid;
            epi(row, col, acc[mi][ni][0], acc[mi][ni][1], acc[mi][ni][2], acc[mi][ni][3]);
        }
}

// ---------------------------------------------------------------------------
// TF32 pipelined MMA core (unchanged R6 config) — used by the projections.
// ---------------------------------------------------------------------------
template<int BM, int BN, int WARPS_M, int WARPS_N, class Epi>
__device__ __forceinline__ void mma_pipe(const float* __restrict__ A,
                                         const float* __restrict__ X,
                                         int Kd, int ldA, int ldX,
                                         int rowBase, char* sbuf, Epi epi)
{
    constexpr int BK      = 16;
    constexpr int THREADS = WARPS_M * WARPS_N * 32;
    constexpr int WM = BM / WARPS_M;
    constexpr int WN = BN / WARPS_N;
    constexpr int MI = WM / 16;
    constexpr int NI = WN / 8;
    constexpr int A_ST = BK + 4;        // 20 floats
    constexpr int A_FLOATS = BM * A_ST;
    constexpr int B_ST = BN + 8;
    constexpr int B_FLOATS = BK * B_ST;

    float* As0 = (float*)sbuf;
    float* As1 = As0 + A_FLOATS;
    float* Bs0 = As1 + A_FLOATS;
    float* Bs1 = Bs0 + B_FLOATS;

    const int tid  = threadIdx.x;
    const int lane = tid & 31;
    const int w    = tid >> 5;
    const int wm   = w / WARPS_N;
    const int wn   = w % WARPS_N;
    const int grp  = lane >> 2;
    const int qid  = lane & 3;

    float acc[MI][NI][4];
#pragma unroll
    for (int mi = 0; mi < MI; ++mi)
#pragma unroll
        for (int ni = 0; ni < NI; ++ni)
#pragma unroll
            for (int r = 0; r < 4; ++r) acc[mi][ni][r] = 0.f;

    auto load_stage = [&](int s, int k0) {
        float* As = s ? As1 : As0;
        float* Bs = s ? Bs1 : Bs0;
#pragma unroll
        for (int i = tid; i < BM * (BK / 4); i += THREADS) {
            int m = i / (BK / 4), kq = i % (BK / 4);
            cp_async16(As + m * A_ST + kq * 4,
                       A + (size_t)(rowBase + m) * ldA + k0 + kq * 4);
        }
#pragma unroll
        for (int i = tid; i < BK * (BN / 4); i += THREADS) {
            int kr = i / (BN / 4), cq = i % (BN / 4);
            cp_async16(Bs + kr * B_ST + cq * 4,
                       X + (size_t)(k0 + kr) * ldX + cq * 4);
        }
    };

    load_stage(0, 0);
    cp_commit();

    const int nIter = Kd / BK;
    for (int it = 0; it < nIter; ++it) {
        const int cur = it & 1;
        if (it + 1 < nIter) {
            load_stage(cur ^ 1, (it + 1) * BK);
            cp_commit();
            cp_wait1();
        } else {
            cp_wait0();
        }
        __syncthreads();

        const float* As = cur ? As1 : As0;
        const float* Bs = cur ? Bs1 : Bs0;

#pragma unroll
        for (int ks = 0; ks < BK / 8; ++ks) {
            const int kb = ks * 8 + qid;
            uint32_t afr[MI][4];
            uint32_t bfr[NI][2];
#pragma unroll
            for (int mi = 0; mi < MI; ++mi) {
                int row = wm * WM + mi * 16 + grp;
                afr[mi][0] = __float_as_uint(As[(row    ) * A_ST + kb    ]);
                afr[mi][1] = __float_as_uint(As[(row + 8) * A_ST + kb    ]);
                afr[mi][2] = __float_as_uint(As[(row    ) * A_ST + kb + 4]);
                afr[mi][3] = __float_as_uint(As[(row + 8) * A_ST + kb + 4]);
            }
#pragma unroll
            for (int ni = 0; ni < NI; ++ni) {
                int col = wn * WN + ni * 8 + grp;
                bfr[ni][0] = __float_as_uint(Bs[(kb    ) * B_ST + col]);
                bfr[ni][1] = __float_as_uint(Bs[(kb + 4) * B_ST + col]);
            }
#pragma unroll
            for (int mi = 0; mi < MI; ++mi)
#pragma unroll
                for (int ni = 0; ni < NI; ++ni)
                    mma_m16n8k8(acc[mi][ni],
                                afr[mi][0], afr[mi][1], afr[mi][2], afr[mi][3],
                                bfr[ni][0], bfr[ni][1]);
        }
        __syncthreads();
    }

#pragma unroll
    for (int mi = 0; mi < MI; ++mi)
#pragma unroll
        for (int ni = 0; ni < NI; ++ni) {
            int row = rowBase + wm * WM + mi * 16 + grp;
            int col = wn * WN + ni * 8 + 2 * qid;
            epi(row, col, acc[mi][ni][0], acc[mi][ni][1], acc[mi][ni][2], acc[mi][ni][3]);
        }
}

// ---------------------------------------------------------------------------
// K0: fold weights (reference's diffusion appends `prev` twice, A^2 x unused),
// interleave gate output columns, combine biases, zero sums.
// ---------------------------------------------------------------------------
__global__ void k0_prep(const float* __restrict__ W0, const float* __restrict__ b0,
                        const float* __restrict__ W1, const float* __restrict__ b1,
                        const float* __restrict__ Wc0, const float* __restrict__ bc0,
                        const float* __restrict__ Wc1, const float* __restrict__ bc1)
{
    int idx    = blockIdx.x * blockDim.x + threadIdx.x;
    int stride = gridDim.x * blockDim.x;

    for (int i = idx; i < 384 * 128; i += stride) {
        int k = i / 128, o = i % 128;
        int orig = (o & 1) ? (o >> 1) + 64 : (o >> 1);
        float v;
        if (k < 128)       { int c = k;        v = W0[orig*384 + 3*c]     + W1[orig*384 + 3*c];     }
        else if (k < 256)  { int c = k - 128;  v = W0[orig*384 + 3*c + 1] + W0[orig*384 + 3*c + 2]; }
        else               { int c = k - 256;  v = W1[orig*384 + 3*c + 1] + W1[orig*384 + 3*c + 2]; }
        g_w1t[i] = v;
    }
    for (int i = idx; i < 384 * 64; i += stride) {
        int k = i / 64, o = i % 64;
        float v;
        if (k < 128)       { int c = k;        v = Wc0[o*384 + 3*c]     + Wc1[o*384 + 3*c];     }
        else if (k < 256)  { int c = k - 128;  v = Wc0[o*384 + 3*c + 1] + Wc0[o*384 + 3*c + 2]; }
        else               { int c = k - 256;  v = Wc1[o*384 + 3*c + 1] + Wc1[o*384 + 3*c + 2]; }
        g_w2t[i] = v;
    }
    for (int i = idx; i < 128; i += stride) {
        int orig = (i & 1) ? (i >> 1) + 64 : (i >> 1);
        g_b1[i] = b0[orig] + b1[orig];
    }
    for (int i = idx; i < 64;  i += stride) g_b2[i] = bc0[i] + bc1[i];
    for (int i = idx; i < NB;  i += stride) { g_rowsum[i] = 0.f; g_colsum[i] = 0.f; }
}

// ---------------------------------------------------------------------------
// K1: Gumbel-softmax adjacency + row/col sums, MUFU-reduced form; fp16 store.
//   a = g1^2 / (g1^2 + E*g0^2),  g_i = EPS - log(u_i+EPS), E = exp(2(l1-l0))
// Sums are computed from the fp32 value (pre-rounding), matching reference.
// ---------------------------------------------------------------------------
__global__ void k1_gumbel(const float* __restrict__ logits,
                          const float* __restrict__ unoise)
{
    __shared__ float scol[8][32];

    const int b  = blockIdx.z;
    const int i0 = blockIdx.y * 32;
    const int j0 = blockIdx.x * 32;
    const int tx = threadIdx.x;
    const int ty = threadIdx.y;

    const float2* lg = reinterpret_cast<const float2*>(logits) + (size_t)b * NSQ;
    const float2* un = reinterpret_cast<const float2*>(unoise) + (size_t)b * NSQ;

    float vals[4];
#pragma unroll
    for (int sI = 0; sI < 4; ++sI) {
        int row  = ty + 8 * sI;
        size_t e = (size_t)(i0 + row) * N_ + (j0 + tx);
        float2 l = lg[e];
        float2 u = un[e];
        float g0 = EPS_ - __logf(u.x + EPS_);
        float g1 = EPS_ - __logf(u.y + EPS_);
        float E  = __expf(2.0f * (l.y - l.x));
        float a  = __fdividef(g1 * g1, fmaf(E, g0 * g0, g1 * g1));
        vals[sI] = a;
        g_adj16[(size_t)b * NSQ + e] = __float2half(a);
    }

#pragma unroll
    for (int sI = 0; sI < 4; ++sI) {
        float v = vals[sI];
#pragma unroll
        for (int o = 16; o > 0; o >>= 1) v += __shfl_down_sync(0xffffffffu, v, o);
        if (tx == 0) atomicAdd(&g_rowsum[b * N_ + i0 + ty + 8 * sI], v);
    }

    scol[ty][tx] = vals[0] + vals[1] + vals[2] + vals[3];
    __syncthreads();
    if (ty == 0) {
        float t2 = 0.f;
#pragma unroll
        for (int w = 0; w < 8; ++w) t2 += scol[w][tx];
        atomicAdd(&g_colsum[b * N_ + j0 + tx], t2);
    }
}

// ---------------------------------------------------------------------------
// K2: xin -> xeff[0..63] (+x16), h -> xeff[64..127] (+x16)
// ---------------------------------------------------------------------------
__global__ void k2_xcat(const float* __restrict__ inp, const float* __restrict__ hx)
{
    size_t idx = (size_t)blockIdx.x * blockDim.x + threadIdx.x;
    if (idx >= (size_t)NB * 128) return;
    size_t node = idx >> 7;
    int c = (int)(idx & 127);
    float v = (c < 64) ? inp[node * 64 + c] : hx[node * 64 + (c - 64)];
    g_xeff[node * 384 + c] = v;
    g_x16[idx] = __float2half(v);
}

// ---------------------------------------------------------------------------
// Shared buffer sizes (bytes)
//   fp16 BN=128: (max(128*40,32*136)=5120 + 32*136=4352) * 2 stages * 2B = 37888
//   fp16 BN=64 : (5120 + 32*72=2304) * 2 * 2                            = 29696
//   tf32 BN=128: (128*20 + 16*136) * 2 * 4                              = 37888
//   tf32 BN=64 : (128*20 + 16*72)  * 2 * 4                              = 29696
// ---------------------------------------------------------------------------
static constexpr int SB_BN128 = 37888;
static constexpr int SB_BN64  = 29696;

// ---------------------------------------------------------------------------
// K3: pass-1 SpMM pair (fp16 MMA). sel0: adj@xcat /(colsum+1) -> cols 128..255;
// sel1: adjT@xcat /(rowsum+1) -> cols 256..383. Epilogue adds identity first.
// ---------------------------------------------------------------------------
__global__ __launch_bounds__(256, 2)
void k3_spmm()
{
    __shared__ __align__(16) char sbuf[SB_BN128];
    int z   = blockIdx.z;
    int b   = z & 15;
    int sel = z >> 4;
    const __half* A    = g_adj16 + (size_t)b * NSQ;
    float*        xeff = g_xeff  + (size_t)b * N_ * 384;
    const float*  sums = (sel ? g_rowsum : g_colsum) + b * N_;
    const int outOff   = 128 + sel * 128;
    const int rowBase  = blockIdx.y * 128;

    auto epi = [&](int row, int col, float v0, float v1, float v2, float v3) {
        float inv0 = 1.f / (sums[row]     + 1.f);
        float inv1 = 1.f / (sums[row + 8] + 1.f);
        float2 x0 = *reinterpret_cast<const float2*>(xeff + (size_t)row       * 384 + col);
        float2 x1 = *reinterpret_cast<const float2*>(xeff + (size_t)(row + 8) * 384 + col);
        float2 o0 = make_float2((v0 + x0.x) * inv0, (v1 + x0.y) * inv0);
        float2 o1 = make_float2((v2 + x1.x) * inv1, (v3 + x1.y) * inv1);
        *reinterpret_cast<float2*>(xeff + (size_t)row       * 384 + outOff + col) = o0;
        *reinterpret_cast<float2*>(xeff + (size_t)(row + 8) * 384 + outOff + col) = o1;
    };

    if (sel == 0)
        mma_pipe_h<128, 128, 2, 4, false>(A, g_x16 + (size_t)b * N_ * 128,
                                          N_, N_, 128, rowBase, sbuf, epi);
    else
        mma_pipe_h<128, 128, 2, 4, true >(A, g_x16 + (size_t)b * N_ * 128,
                                          N_, N_, 128, rowBase, sbuf, epi);
}

// ---------------------------------------------------------------------------
// K4b: gate projection (tf32) + fused activation epilogue.
// col even -> r, col odd -> u. Writes u, r*h (fp32 into xeff + fp16 copy).
// ---------------------------------------------------------------------------
__global__ __launch_bounds__(256, 2)
void k4b_gate(const float* __restrict__ hx)
{
    __shared__ __align__(16) char sbuf[SB_BN128];
    const int rowBase = blockIdx.y * 128;

    auto epi = [&](int row, int col, float v0, float v1, float v2, float v3) {
        int o = col >> 1;
        float b_r = g_b1[col], b_u = g_b1[col + 1];
        float r0 = 1.f / (1.f + __expf(-(v0 + b_r)));
        float u0 = 1.f / (1.f + __expf(-(v1 + b_u)));
        float r1 = 1.f / (1.f + __expf(-(v2 + b_r)));
        float u1 = 1.f / (1.f + __expf(-(v3 + b_u)));
        float rh0 = r0 * hx[(size_t)row * 64 + o];
        float rh1 = r1 * hx[(size_t)(row + 8) * 64 + o];
        g_u[(size_t)row * 64 + o]       = u0;
        g_u[(size_t)(row + 8) * 64 + o] = u1;
        g_xeff[(size_t)row * 384 + 64 + o]       = rh0;
        g_xeff[(size_t)(row + 8) * 384 + 64 + o] = rh1;
        g_rh16[(size_t)row * 64 + o]       = __float2half(rh0);
        g_rh16[(size_t)(row + 8) * 64 + o] = __float2half(rh1);
    };

    mma_pipe<128, 128, 2, 4>(g_xeff, g_w1t, 384, 384, 128, rowBase, sbuf, epi);
}

// ---------------------------------------------------------------------------
// K6: pass-2 SpMM pair over r*h (fp16 MMA).
// sel0 -> Q0 cols 192..255 (colsum), sel1 -> Q1 cols 320..383 (rowsum).
// ---------------------------------------------------------------------------
__global__ __launch_bounds__(256, 2)
void k6_spmm()
{
    __shared__ __align__(16) char sbuf[SB_BN64];
    int z   = blockIdx.z;
    int b   = z & 15;
    int sel = z >> 4;
    const __half* A    = g_adj16 + (size_t)b * NSQ;
    float*        xeff = g_xeff  + (size_t)b * N_ * 384;
    const float*  sums = (sel ? g_rowsum : g_colsum) + b * N_;
    const int outOff   = 192 + sel * 128;
    const int rowBase  = blockIdx.y * 128;

    auto epi = [&](int row, int col, float v0, float v1, float v2, float v3) {
        float inv0 = 1.f / (sums[row]     + 1.f);
        float inv1 = 1.f / (sums[row + 8] + 1.f);
        float2 x0 = *reinterpret_cast<const float2*>(xeff + (size_t)row       * 384 + 64 + col);
        float2 x1 = *reinterpret_cast<const float2*>(xeff + (size_t)(row + 8) * 384 + 64 + col);
        float2 o0 = make_float2((v0 + x0.x) * inv0, (v1 + x0.y) * inv0);
        float2 o1 = make_float2((v2 + x1.x) * inv1, (v3 + x1.y) * inv1);
        *reinterpret_cast<float2*>(xeff + (size_t)row       * 384 + outOff + col) = o0;
        *reinterpret_cast<float2*>(xeff + (size_t)(row + 8) * 384 + outOff + col) = o1;
    };

    if (sel == 0)
        mma_pipe_h<128, 64, 4, 2, false>(A, g_rh16 + (size_t)b * N_ * 64,
                                         N_, N_, 64, rowBase, sbuf, epi);
    else
        mma_pipe_h<128, 64, 4, 2, true >(A, g_rh16 + (size_t)b * N_ * 64,
                                         N_, N_, 64, rowBase, sbuf, epi);
}

// ---------------------------------------------------------------------------
// K8: candidate projection (tf32) + fused final GRU epilogue.
// c = tanh(xeff @ w2t + b2); out = u*h + (1-u)*c
// ---------------------------------------------------------------------------
__global__ __launch_bounds__(256, 2)
void k8_cand(const float* __restrict__ hx, float* __restrict__ out)
{
    __shared__ __align__(16) char sbuf[SB_BN64];
    const int rowBase = blockIdx.y * 128;

    auto epi = [&](int row, int col, float v0, float v1, float v2, float v3) {
        float b0v = g_b2[col], b1v = g_b2[col + 1];
        float c00 = tanhf(v0 + b0v), c01 = tanhf(v1 + b1v);
        float c10 = tanhf(v2 + b0v), c11 = tanhf(v3 + b1v);
        size_t i0 = (size_t)row * 64 + col;
        size_t i1 = (size_t)(row + 8) * 64 + col;
        float2 u0 = *reinterpret_cast<const float2*>(g_u + i0);
        float2 u1 = *reinterpret_cast<const float2*>(g_u + i1);
        float2 h0 = *reinterpret_cast<const float2*>(hx + i0);
        float2 h1 = *reinterpret_cast<const float2*>(hx + i1);
        float2 o0 = make_float2(u0.x * h0.x + (1.f - u0.x) * c00,
                                u0.y * h0.y + (1.f - u0.y) * c01);
        float2 o1 = make_float2(u1.x * h1.x + (1.f - u1.x) * c10,
                                u1.y * h1.y + (1.f - u1.y) * c11);
        *reinterpret_cast<float2*>(out + i0) = o0;
        *reinterpret_cast<float2*>(out + i1) = o1;
    };

    mma_pipe<128, 64, 4, 2>(g_xeff, g_w2t, 384, 384, 64, rowBase, sbuf, epi);
}

// ---------------------------------------------------------------------------
// Launch: kernel launches only (graph-capture safe)
// ---------------------------------------------------------------------------
extern "C" void kernel_launch(void* const* d_in, const int* in_sizes, int n_in,
                              void* d_out, int out_size)
{
    const float* logits = (const float*)d_in[0];
    const float* unoise = (const float*)d_in[1];
    const float* inputs = (const float*)d_in[2];
    const float* hx     = (const float*)d_in[3];
    const float* W0     = (const float*)d_in[4];
    const float* b0     = (const float*)d_in[5];
    const float* W1     = (const float*)d_in[6];
    const float* b1     = (const float*)d_in[7];
    const float* Wc0    = (const float*)d_in[8];
    const float* bc0    = (const float*)d_in[9];
    const float* Wc1    = (const float*)d_in[10];
    const float* bc1    = (const float*)d_in[11];
    float* out          = (float*)d_out;

    k0_prep<<<128, 256>>>(W0, b0, W1, b1, Wc0, bc0, Wc1, bc1);

    k1_gumbel<<<dim3(N_/32, N_/32, B_), dim3(32, 8)>>>(logits, unoise);

    k2_xcat<<<(NB * 128 + 255) / 256, 256>>>(inputs, hx);

    k3_spmm<<<dim3(1, N_/128, 2 * B_), 256>>>();

    k4b_gate<<<dim3(1, NB/128, 1), 256>>>(hx);

    k6_spmm<<<dim3(1, N_/128, 2 * B_), 256>>>();

    k8_cand<<<dim3(1, NB/128, 1), 256>>>(hx, out);
}

// round 12
// speedup vs baseline: 1.4698x; 1.0863x over previous
#include <cuda_runtime.h>
#include <cuda_fp16.h>
#include <cstdint>

// Problem constants
static constexpr int   B_   = 16;
static constexpr int   N_   = 1024;
static constexpr float EPS_ = 1e-10f;
static constexpr int   NSQ  = N_ * N_;        // 1048576
static constexpr int   NB   = B_ * N_;        // 16384 nodes total

// ---------------------------------------------------------------------------
// Scratch (device globals; allocation is forbidden)
// xeff16 layout per node (384 halves) — the ONLY feature buffer (all fp16):
//   [  0.. 63] xin
//   [ 64..127] h        (pass 1)  ->  r*h   (overwritten by k4b epilogue)
//   [128..191] P0x = ((adj @x)+x)_xin * invc
//   [192..255] P0h (pass 1)       ->  Q0 = ((adj @rh)+rh)*invc (k6 epilogue)
//   [256..319] P1x = ((adjT@x)+x)_xin * invr
//   [320..383] P1h (pass 1)       ->  Q1 = ((adjT@rh)+rh)*invr (k6 epilogue)
// ---------------------------------------------------------------------------
__device__ __half g_adj16[B_ * NSQ];         // 32 MB  adj[b,i,j] fp16
__device__ float  g_rowsum[NB];              // sum_j adj[i,j] (fp32)
__device__ float  g_colsum[NB];              // sum_i adj[i,j]
__device__ __half g_xeff16[NB * 384];        // 12.6 MB unified feature buffer
__device__ float  g_u    [NB * 64];          // update gate (fp32)
__device__ __half g_w1t  [384 * 128];        // gate weights fp16, (k,o') interleaved r/u
__device__ __half g_w2t  [384 * 64];         // candidate weights fp16, (k,o)
__device__ float  g_b1   [128];              // interleaved r/u bias
__device__ float  g_b2   [64];

// ---------------------------------------------------------------------------
// cp.async helpers
// ---------------------------------------------------------------------------
__device__ __forceinline__ void cp_async16(void* smem_dst, const void* gsrc)
{
    uint32_t s = (uint32_t)__cvta_generic_to_shared(smem_dst);
    asm volatile("cp.async.cg.shared.global [%0], [%1], 16;\n" :: "r"(s), "l"(gsrc));
}
__device__ __forceinline__ void cp_commit() { asm volatile("cp.async.commit_group;\n"); }
__device__ __forceinline__ void cp_wait1()  { asm volatile("cp.async.wait_group 1;\n"); }
__device__ __forceinline__ void cp_wait0()  { asm volatile("cp.async.wait_group 0;\n"); }

__device__ __forceinline__ void mma_m16n8k16h(float c[4],
                                              uint32_t a0, uint32_t a1, uint32_t a2, uint32_t a3,
                                              uint32_t b0, uint32_t b1)
{
    asm volatile("mma.sync.aligned.m16n8k16.row.col.f32.f16.f16.f32 "
                 "{%0,%1,%2,%3}, {%4,%5,%6,%7}, {%8,%9}, {%0,%1,%2,%3};\n"
                 : "+f"(c[0]), "+f"(c[1]), "+f"(c[2]), "+f"(c[3])
                 : "r"(a0), "r"(a1), "r"(a2), "r"(a3), "r"(b0), "r"(b1));
}

// pack two non-adjacent halves into one 32-bit MMA operand (lo, hi)
__device__ __forceinline__ uint32_t pack2(const __half* p0, const __half* p1)
{
    unsigned short lo = *(const unsigned short*)p0;
    unsigned short hi = *(const unsigned short*)p1;
    return (uint32_t)lo | ((uint32_t)hi << 16);
}

// ---------------------------------------------------------------------------
// FP16 pipelined MMA core (m16n8k16, BK=32, double-buffered cp.async).
//   AKM=false: A row-major  (element (m,k) at A[m*ldA+k]); smem [BM][40]
//   AKM=true : A K-major    (element (m,k) at A[k*ldA+m]); smem [32][BM+8]
// fp32 accumulate. Epi(rowGlobal, colLocal, v0..v3) at (row,col),(row,col+1),
// (row+8,col),(row+8,col+1); col always even.
// ---------------------------------------------------------------------------
template<int BM, int BN, int WARPS_M, int WARPS_N, bool AKM, class Epi>
__device__ __forceinline__ void mma_pipe_h(const __half* __restrict__ A,
                                           const __half* __restrict__ X,
                                           int Kd, int ldA, int ldX,
                                           int rowBase, char* sbuf, Epi epi)
{
    constexpr int BK      = 32;
    constexpr int THREADS = WARPS_M * WARPS_N * 32;
    constexpr int WM = BM / WARPS_M;
    constexpr int WN = BN / WARPS_N;
    constexpr int MI = WM / 16;
    constexpr int NI = WN / 8;
    constexpr int LDA_RM = BK + 8;          // 40 halves
    constexpr int LDM_KM = BM + 8;          // 136 halves
    constexpr int A_HALVES = AKM ? BK * LDM_KM : BM * LDA_RM;
    constexpr int LDB = BN + 8;
    constexpr int B_HALVES = BK * LDB;

    __half* As0 = (__half*)sbuf;
    __half* As1 = As0 + A_HALVES;
    __half* Bs0 = As1 + A_HALVES;
    __half* Bs1 = Bs0 + B_HALVES;

    const int tid  = threadIdx.x;
    const int lane = tid & 31;
    const int w    = tid >> 5;
    const int wm   = w / WARPS_N;
    const int wn   = w % WARPS_N;
    const int grp  = lane >> 2;     // 0..7
    const int qid  = lane & 3;      // 0..3

    float acc[MI][NI][4];
#pragma unroll
    for (int mi = 0; mi < MI; ++mi)
#pragma unroll
        for (int ni = 0; ni < NI; ++ni)
#pragma unroll
            for (int r = 0; r < 4; ++r) acc[mi][ni][r] = 0.f;

    auto load_stage = [&](int s, int k0) {
        __half* As = s ? As1 : As0;
        __half* Bs = s ? Bs1 : Bs0;
        if (AKM) {
#pragma unroll
            for (int i = tid; i < BK * (BM / 8); i += THREADS) {
                int kr = i / (BM / 8), mq = i % (BM / 8);
                cp_async16(As + kr * LDM_KM + mq * 8,
                           A + (size_t)(k0 + kr) * ldA + rowBase + mq * 8);
            }
        } else {
#pragma unroll
            for (int i = tid; i < BM * (BK / 8); i += THREADS) {
                int m = i / (BK / 8), kq = i % (BK / 8);
                cp_async16(As + m * LDA_RM + kq * 8,
                           A + (size_t)(rowBase + m) * ldA + k0 + kq * 8);
            }
        }
#pragma unroll
        for (int i = tid; i < BK * (BN / 8); i += THREADS) {
            int kr = i / (BN / 8), cq = i % (BN / 8);
            cp_async16(Bs + kr * LDB + cq * 8,
                       X + (size_t)(k0 + kr) * ldX + cq * 8);
        }
    };

    load_stage(0, 0);
    cp_commit();

    const int nIter = Kd / BK;
    for (int it = 0; it < nIter; ++it) {
        const int cur = it & 1;
        if (it + 1 < nIter) {
            load_stage(cur ^ 1, (it + 1) * BK);
            cp_commit();
            cp_wait1();
        } else {
            cp_wait0();
        }
        __syncthreads();

        const __half* As = cur ? As1 : As0;
        const __half* Bs = cur ? Bs1 : Bs0;

#pragma unroll
        for (int ks = 0; ks < 2; ++ks) {           // two K=16 steps per BK=32
            const int kh = ks * 16 + 2 * qid;
            uint32_t afr[MI][4];
            uint32_t bfr[NI][2];
#pragma unroll
            for (int mi = 0; mi < MI; ++mi) {
                int row = wm * WM + mi * 16 + grp;
                if (AKM) {
                    afr[mi][0] = pack2(&As[(kh    ) * LDM_KM + row    ], &As[(kh + 1) * LDM_KM + row    ]);
                    afr[mi][1] = pack2(&As[(kh    ) * LDM_KM + row + 8], &As[(kh + 1) * LDM_KM + row + 8]);
                    afr[mi][2] = pack2(&As[(kh + 8) * LDM_KM + row    ], &As[(kh + 9) * LDM_KM + row    ]);
                    afr[mi][3] = pack2(&As[(kh + 8) * LDM_KM + row + 8], &As[(kh + 9) * LDM_KM + row + 8]);
                } else {
                    afr[mi][0] = *(const uint32_t*)(As + (row    ) * LDA_RM + kh);
                    afr[mi][1] = *(const uint32_t*)(As + (row + 8) * LDA_RM + kh);
                    afr[mi][2] = *(const uint32_t*)(As + (row    ) * LDA_RM + kh + 8);
                    afr[mi][3] = *(const uint32_t*)(As + (row + 8) * LDA_RM + kh + 8);
                }
            }
#pragma unroll
            for (int ni = 0; ni < NI; ++ni) {
                int col = wn * WN + ni * 8 + grp;
                bfr[ni][0] = pack2(&Bs[(kh    ) * LDB + col], &Bs[(kh + 1) * LDB + col]);
                bfr[ni][1] = pack2(&Bs[(kh + 8) * LDB + col], &Bs[(kh + 9) * LDB + col]);
            }
#pragma unroll
            for (int mi = 0; mi < MI; ++mi)
#pragma unroll
                for (int ni = 0; ni < NI; ++ni)
                    mma_m16n8k16h(acc[mi][ni],
                                  afr[mi][0], afr[mi][1], afr[mi][2], afr[mi][3],
                                  bfr[ni][0], bfr[ni][1]);
        }
        __syncthreads();
    }

#pragma unroll
    for (int mi = 0; mi < MI; ++mi)
#pragma unroll
        for (int ni = 0; ni < NI; ++ni) {
            int row = rowBase + wm * WM + mi * 16 + grp;
            int col = wn * WN + ni * 8 + 2 * qid;
            epi(row, col, acc[mi][ni][0], acc[mi][ni][1], acc[mi][ni][2], acc[mi][ni][3]);
        }
}

// ---------------------------------------------------------------------------
// K0: fold weights (reference's diffusion appends `prev` twice, A^2 x unused)
// -> fp16; interleave gate output columns; combine biases; zero sums.
// ---------------------------------------------------------------------------
__global__ void k0_prep(const float* __restrict__ W0, const float* __restrict__ b0,
                        const float* __restrict__ W1, const float* __restrict__ b1,
                        const float* __restrict__ Wc0, const float* __restrict__ bc0,
                        const float* __restrict__ Wc1, const float* __restrict__ bc1)
{
    int idx    = blockIdx.x * blockDim.x + threadIdx.x;
    int stride = gridDim.x * blockDim.x;

    for (int i = idx; i < 384 * 128; i += stride) {
        int k = i / 128, o = i % 128;
        int orig = (o & 1) ? (o >> 1) + 64 : (o >> 1);
        float v;
        if (k < 128)       { int c = k;        v = W0[orig*384 + 3*c]     + W1[orig*384 + 3*c];     }
        else if (k < 256)  { int c = k - 128;  v = W0[orig*384 + 3*c + 1] + W0[orig*384 + 3*c + 2]; }
        else               { int c = k - 256;  v = W1[orig*384 + 3*c + 1] + W1[orig*384 + 3*c + 2]; }
        g_w1t[i] = __float2half(v);
    }
    for (int i = idx; i < 384 * 64; i += stride) {
        int k = i / 64, o = i % 64;
        float v;
        if (k < 128)       { int c = k;        v = Wc0[o*384 + 3*c]     + Wc1[o*384 + 3*c];     }
        else if (k < 256)  { int c = k - 128;  v = Wc0[o*384 + 3*c + 1] + Wc0[o*384 + 3*c + 2]; }
        else               { int c = k - 256;  v = Wc1[o*384 + 3*c + 1] + Wc1[o*384 + 3*c + 2]; }
        g_w2t[i] = __float2half(v);
    }
    for (int i = idx; i < 128; i += stride) {
        int orig = (i & 1) ? (i >> 1) + 64 : (i >> 1);
        g_b1[i] = b0[orig] + b1[orig];
    }
    for (int i = idx; i < 64;  i += stride) g_b2[i] = bc0[i] + bc1[i];
    for (int i = idx; i < NB;  i += stride) { g_rowsum[i] = 0.f; g_colsum[i] = 0.f; }
}

// ---------------------------------------------------------------------------
// fast -ln(x) on the FMA pipe (no MUFU): exact exponent split + binade-folded
// mantissa (m in [2/3,4/3), |z|<=1/3) + degree-8 Taylor of ln(1+z).
// Truncation <= 9e-6 absolute, relative-exact as z->0. g enters only SQUARED
// downstream, so a sign flip of a tiny g is harmless.
// Returns EPS - ln(x), matching the reference's gumbel inner term.
// ---------------------------------------------------------------------------
__device__ __forceinline__ float fast_nlog(float x)
{
    int   i = __float_as_int(x);
    int   e = (i >> 23) - 127;
    float m = __int_as_float((i & 0x7FFFFF) | 0x3F800000);   // [1,2)
    if (m > 1.3333334f) { m *= 0.5f; e += 1; }               // -> [2/3, 4/3)
    float z = m - 1.0f;                                      // |z| <= 1/3
    float q = fmaf(z, -0.125f,      0.14285715f);
    q = fmaf(z, q, -0.16666667f);
    q = fmaf(z, q,  0.2f);
    q = fmaf(z, q, -0.25f);
    q = fmaf(z, q,  0.33333334f);
    q = fmaf(z, q, -0.5f);
    q = fmaf(z, q,  1.0f);
    float lnx = fmaf((float)e, 0.69314718f, z * q);
    return EPS_ - lnx;
}

// ---------------------------------------------------------------------------
// K1: Gumbel-softmax adjacency + row/col sums; 2 MUFU/pair (exp + div).
//   a = g1^2 / (g1^2 + E*g0^2),  g_i = EPS - ln(u_i+EPS), E = exp(2(l1-l0))
// ---------------------------------------------------------------------------
__global__ void k1_gumbel(const float* __restrict__ logits,
                          const float* __restrict__ unoise)
{
    __shared__ float scol[8][32];

    const int b  = blockIdx.z;
    const int i0 = blockIdx.y * 32;
    const int j0 = blockIdx.x * 32;
    const int tx = threadIdx.x;
    const int ty = threadIdx.y;

    const float2* lg = reinterpret_cast<const float2*>(logits) + (size_t)b * NSQ;
    const float2* un = reinterpret_cast<const float2*>(unoise) + (size_t)b * NSQ;

    float vals[4];
#pragma unroll
    for (int sI = 0; sI < 4; ++sI) {
        int row  = ty + 8 * sI;
        size_t e = (size_t)(i0 + row) * N_ + (j0 + tx);
        float2 l = lg[e];
        float2 u = un[e];
        float g0 = fast_nlog(u.x + EPS_);
        float g1 = fast_nlog(u.y + EPS_);
        float E  = __expf(2.0f * (l.y - l.x));
        float a  = __fdividef(g1 * g1, fmaf(E, g0 * g0, g1 * g1));
        vals[sI] = a;
        g_adj16[(size_t)b * NSQ + e] = __float2half(a);
    }

#pragma unroll
    for (int sI = 0; sI < 4; ++sI) {
        float v = vals[sI];
#pragma unroll
        for (int o = 16; o > 0; o >>= 1) v += __shfl_down_sync(0xffffffffu, v, o);
        if (tx == 0) atomicAdd(&g_rowsum[b * N_ + i0 + ty + 8 * sI], v);
    }

    scol[ty][tx] = vals[0] + vals[1] + vals[2] + vals[3];
    __syncthreads();
    if (ty == 0) {
        float t2 = 0.f;
#pragma unroll
        for (int w = 0; w < 8; ++w) t2 += scol[w][tx];
        atomicAdd(&g_colsum[b * N_ + j0 + tx], t2);
    }
}

// ---------------------------------------------------------------------------
// K2: xin -> xeff16[0..63], h -> xeff16[64..127]
// ---------------------------------------------------------------------------
__global__ void k2_xcat(const float* __restrict__ inp, const float* __restrict__ hx)
{
    size_t idx = (size_t)blockIdx.x * blockDim.x + threadIdx.x;
    if (idx >= (size_t)NB * 128) return;
    size_t node = idx >> 7;
    int c = (int)(idx & 127);
    float v = (c < 64) ? inp[node * 64 + c] : hx[node * 64 + (c - 64)];
    g_xeff16[node * 384 + c] = __float2half(v);
}

// ---------------------------------------------------------------------------
// Shared buffer sizes (bytes)
//   BN=128: (max(128*40, 32*136)=5120 + 32*136=4352) * 2 stages * 2B = 37888
//   BN=64 : (5120 + 32*72=2304) * 2 * 2                              = 29696
// ---------------------------------------------------------------------------
static constexpr int SB_BN128 = 37888;
static constexpr int SB_BN64  = 29696;

// ---------------------------------------------------------------------------
// K3: pass-1 SpMM pair. sel0: adj@xcat /(colsum+1) -> cols 128..255;
// sel1: adjT@xcat /(rowsum+1) -> cols 256..383. Identity added pre-scale.
// ---------------------------------------------------------------------------
__global__ __launch_bounds__(256, 2)
void k3_spmm()
{
    __shared__ __align__(16) char sbuf[SB_BN128];
    int z   = blockIdx.z;
    int b   = z & 15;
    int sel = z >> 4;
    const __half* A    = g_adj16  + (size_t)b * NSQ;
    __half*       xeff = g_xeff16 + (size_t)b * N_ * 384;
    const float*  sums = (sel ? g_rowsum : g_colsum) + b * N_;
    const int outOff   = 128 + sel * 128;
    const int rowBase  = blockIdx.y * 128;

    auto epi = [&](int row, int col, float v0, float v1, float v2, float v3) {
        float inv0 = 1.f / (sums[row]     + 1.f);
        float inv1 = 1.f / (sums[row + 8] + 1.f);
        __half2 x0 = *reinterpret_cast<const __half2*>(xeff + (size_t)row       * 384 + col);
        __half2 x1 = *reinterpret_cast<const __half2*>(xeff + (size_t)(row + 8) * 384 + col);
        float2 xf0 = __half22float2(x0);
        float2 xf1 = __half22float2(x1);
        *reinterpret_cast<__half2*>(xeff + (size_t)row       * 384 + outOff + col) =
            __floats2half2_rn((v0 + xf0.x) * inv0, (v1 + xf0.y) * inv0);
        *reinterpret_cast<__half2*>(xeff + (size_t)(row + 8) * 384 + outOff + col) =
            __floats2half2_rn((v2 + xf1.x) * inv1, (v3 + xf1.y) * inv1);
    };

    if (sel == 0)
        mma_pipe_h<128, 128, 2, 4, false>(A, xeff, N_, N_, 384, rowBase, sbuf, epi);
    else
        mma_pipe_h<128, 128, 2, 4, true >(A, xeff, N_, N_, 384, rowBase, sbuf, epi);
}

// ---------------------------------------------------------------------------
// K4b: gate projection (fp16, A = full xeff16 rows, K=384) + fused epilogue.
// col even -> r, col odd -> u. Writes u (fp32) and r*h (fp16 into cols 64..127).
// ---------------------------------------------------------------------------
__global__ __launch_bounds__(256, 2)
void k4b_gate(const float* __restrict__ hx)
{
    __shared__ __align__(16) char sbuf[SB_BN128];
    const int rowBase = blockIdx.y * 128;

    auto epi = [&](int row, int col, float v0, float v1, float v2, float v3) {
        int o = col >> 1;
        float b_r = g_b1[col], b_u = g_b1[col + 1];
        float r0 = 1.f / (1.f + __expf(-(v0 + b_r)));
        float u0 = 1.f / (1.f + __expf(-(v1 + b_u)));
        float r1 = 1.f / (1.f + __expf(-(v2 + b_r)));
        float u1 = 1.f / (1.f + __expf(-(v3 + b_u)));
        float rh0 = r0 * hx[(size_t)row * 64 + o];
        float rh1 = r1 * hx[(size_t)(row + 8) * 64 + o];
        g_u[(size_t)row * 64 + o]       = u0;
        g_u[(size_t)(row + 8) * 64 + o] = u1;
        g_xeff16[(size_t)row * 384 + 64 + o]       = __float2half(rh0);
        g_xeff16[(size_t)(row + 8) * 384 + 64 + o] = __float2half(rh1);
    };

    mma_pipe_h<128, 128, 2, 4, false>(g_xeff16, g_w1t, 384, 384, 128, rowBase, sbuf, epi);
}

// ---------------------------------------------------------------------------
// K6: pass-2 SpMM pair over r*h (xeff16 cols 64..127 as B operand).
// sel0 -> Q0 cols 192..255 (colsum), sel1 -> Q1 cols 320..383 (rowsum).
// ---------------------------------------------------------------------------
__global__ __launch_bounds__(256, 2)
void k6_spmm()
{
    __shared__ __align__(16) char sbuf[SB_BN64];
    int z   = blockIdx.z;
    int b   = z & 15;
    int sel = z >> 4;
    const __half* A    = g_adj16  + (size_t)b * NSQ;
    __half*       xeff = g_xeff16 + (size_t)b * N_ * 384;
    const float*  sums = (sel ? g_rowsum : g_colsum) + b * N_;
    const int outOff   = 192 + sel * 128;
    const int rowBase  = blockIdx.y * 128;

    auto epi = [&](int row, int col, float v0, float v1, float v2, float v3) {
        float inv0 = 1.f / (sums[row]     + 1.f);
        float inv1 = 1.f / (sums[row + 8] + 1.f);
        __half2 x0 = *reinterpret_cast<const __half2*>(xeff + (size_t)row       * 384 + 64 + col);
        __half2 x1 = *reinterpret_cast<const __half2*>(xeff + (size_t)(row + 8) * 384 + 64 + col);
        float2 xf0 = __half22float2(x0);
        float2 xf1 = __half22float2(x1);
        *reinterpret_cast<__half2*>(xeff + (size_t)row       * 384 + outOff + col) =
            __floats2half2_rn((v0 + xf0.x) * inv0, (v1 + xf0.y) * inv0);
        *reinterpret_cast<__half2*>(xeff + (size_t)(row + 8) * 384 + outOff + col) =
            __floats2half2_rn((v2 + xf1.x) * inv1, (v3 + xf1.y) * inv1);
    };

    if (sel == 0)
        mma_pipe_h<128, 64, 4, 2, false>(A, xeff + 64, N_, N_, 384, rowBase, sbuf, epi);
    else
        mma_pipe_h<128, 64, 4, 2, true >(A, xeff + 64, N_, N_, 384, rowBase, sbuf, epi);
}

// ---------------------------------------------------------------------------
// K8: candidate projection (fp16) + fused final GRU epilogue.
// c = tanh(xeff @ w2t + b2); out = u*h + (1-u)*c
// ---------------------------------------------------------------------------
__global__ __launch_bounds__(256, 2)
void k8_cand(const float* __restrict__ hx, float* __restrict__ out)
{
    __shared__ __align__(16) char sbuf[SB_BN64];
    const int rowBase = blockIdx.y * 128;

    auto epi = [&](int row, int col, float v0, float v1, float v2, float v3) {
        float b0v = g_b2[col], b1v = g_b2[col + 1];
        float c00 = tanhf(v0 + b0v), c01 = tanhf(v1 + b1v);
        float c10 = tanhf(v2 + b0v), c11 = tanhf(v3 + b1v);
        size_t i0 = (size_t)row * 64 + col;
        size_t i1 = (size_t)(row + 8) * 64 + col;
        float2 u0 = *reinterpret_cast<const float2*>(g_u + i0);
        float2 u1 = *reinterpret_cast<const float2*>(g_u + i1);
        float2 h0 = *reinterpret_cast<const float2*>(hx + i0);
        float2 h1 = *reinterpret_cast<const float2*>(hx + i1);
        float2 o0 = make_float2(u0.x * h0.x + (1.f - u0.x) * c00,
                                u0.y * h0.y + (1.f - u0.y) * c01);
        float2 o1 = make_float2(u1.x * h1.x + (1.f - u1.x) * c10,
                                u1.y * h1.y + (1.f - u1.y) * c11);
        *reinterpret_cast<float2*>(out + i0) = o0;
        *reinterpret_cast<float2*>(out + i1) = o1;
    };

    mma_pipe_h<128, 64, 4, 2, false>(g_xeff16, g_w2t, 384, 384, 64, rowBase, sbuf, epi);
}

// ---------------------------------------------------------------------------
// Launch: kernel launches only (graph-capture safe)
// ---------------------------------------------------------------------------
extern "C" void kernel_launch(void* const* d_in, const int* in_sizes, int n_in,
                              void* d_out, int out_size)
{
    const float* logits = (const float*)d_in[0];
    const float* unoise = (const float*)d_in[1];
    const float* inputs = (const float*)d_in[2];
    const float* hx     = (const float*)d_in[3];
    const float* W0     = (const float*)d_in[4];
    const float* b0     = (const float*)d_in[5];
    const float* W1     = (const float*)d_in[6];
    const float* b1     = (const float*)d_in[7];
    const float* Wc0    = (const float*)d_in[8];
    const float* bc0    = (const float*)d_in[9];
    const float* Wc1    = (const float*)d_in[10];
    const float* bc1    = (const float*)d_in[11];
    float* out          = (float*)d_out;

    k0_prep<<<128, 256>>>(W0, b0, W1, b1, Wc0, bc0, Wc1, bc1);

    k1_gumbel<<<dim3(N_/32, N_/32, B_), dim3(32, 8)>>>(logits, unoise);

    k2_xcat<<<(NB * 128 + 255) / 256, 256>>>(inputs, hx);

    k3_spmm<<<dim3(1, N_/128, 2 * B_), 256>>>();

    k4b_gate<<<dim3(1, NB/128, 1), 256>>>(hx);

    k6_spmm<<<dim3(1, N_/128, 2 * B_), 256>>>();

    k8_cand<<<dim3(1, NB/128, 1), 256>>>(hx, out);
}